// round 6
// baseline (speedup 1.0000x reference)
#include <cuda_runtime.h>
#include <cuda_bf16.h>
#include <math.h>
#include <stdint.h>

// Problem constants
#define B_ 4
#define T_ 1024
#define E_ 1024
#define H_ 8
#define DH_ 128
#define KV_ 2304
#define CML_ 256
#define MEML_ 1024
#define TOTMEM_ 1280
#define SCALE_ 0.08838834764831845f

// Scratch (device globals — allocation-free rule)
__device__ float g_q[B_ * T_ * E_];
__device__ float g_k[B_ * KV_ * E_];
__device__ float g_v[B_ * KV_ * E_];
__device__ float g_attn[B_ * T_ * E_];
__device__ float g_cwt[1024 * 4096];   // conv_w permuted to (o, r*1024+d)

#define MODE_Q 0
#define MODE_KV 1
#define MODE_OUT 3
#define MODE_CMEM 4

__device__ __forceinline__ uint32_t tf32r(float f) {
    uint32_t r;
    asm("cvt.rna.tf32.f32 %0, %1;" : "=r"(r) : "f"(f));
    return r;
}

#define MMA_TF32(c, a0, a1, a2, a3, b0, b1) \
    asm volatile( \
        "mma.sync.aligned.m16n8k8.row.col.f32.tf32.tf32.f32 " \
        "{%0,%1,%2,%3}, {%4,%5,%6,%7}, {%8,%9}, {%0,%1,%2,%3};" \
        : "+f"((c)[0]), "+f"((c)[1]), "+f"((c)[2]), "+f"((c)[3]) \
        : "r"(a0), "r"(a1), "r"(a2), "r"(a3), "r"(b0), "r"(b1))

// ---------------------------------------------------------------------------
// tf32 mma.sync GEMM: 128x128x32 block tile, 8 warps, warp tile 32x64
// ---------------------------------------------------------------------------
template <int MODE>
__global__ void __launch_bounds__(256) mma_gemm(
    const float* __restrict__ A0, const float* __restrict__ A1,
    const float* __restrict__ A2, const float* __restrict__ Bmat,
    const float* __restrict__ bias, float* __restrict__ Cout)
{
    constexpr int K    = (MODE == MODE_CMEM) ? 4096 : 1024;
    constexpr int LDA  = (MODE == MODE_CMEM) ? 4096 : 1024;
    constexpr int LDBN = (MODE == MODE_KV) ? 2048 : 1024;
    constexpr bool BT  = (MODE == MODE_CMEM);
    constexpr int NT   = K / 32;

    __shared__ uint32_t As[32][132];
    __shared__ uint32_t Bs[32][132];

    const int tid = threadIdx.x;
    const int wid = tid >> 5;
    const int lid = tid & 31;
    const int g   = lid >> 2;
    const int tg  = lid & 3;
    const int m0 = blockIdx.y * 128;
    const int n0 = blockIdx.x * 128;
    const int wm = (wid & 3) * 32;
    const int wn = (wid >> 2) * 64;

    const float* Abase;
    const float* Bbase;
    if constexpr (MODE == MODE_Q) {
        Abase = A0 + (size_t)m0 * 1024;
        Bbase = Bmat + n0;
    } else if constexpr (MODE == MODE_KV) {
        int b = m0 / KV_;
        int j = m0 - b * KV_;
        if (j < CML_)              Abase = A2 + (size_t)(b * CML_ + j) * 1024;
        else if (j < CML_ + MEML_) Abase = A1 + (size_t)(b * MEML_ + (j - CML_)) * 1024;
        else                       Abase = A0 + (size_t)(b * T_ + (j - CML_ - MEML_)) * 1024;
        Bbase = Bmat + n0;
    } else if constexpr (MODE == MODE_OUT) {
        Abase = g_attn + (size_t)m0 * 1024;
        Bbase = Bmat + n0;
    } else { // CMEM
        Abase = A1 + (size_t)m0 * 4096;
        Bbase = Bmat + (size_t)n0 * 4096;
    }

    const int arow = tid >> 1;
    const int akh  = (tid & 1) * 16;
    const float* aPtr = Abase + (size_t)arow * LDA + akh;

    float4 av[4], bv[4];
    auto loadA = [&](int t) {
        const float* p = aPtr + t * 32;
#pragma unroll
        for (int j = 0; j < 4; j++) av[j] = *(const float4*)(p + 4 * j);
    };
    auto loadB = [&](int t) {
        if constexpr (BT) {
            const float* p = Bbase + (size_t)(tid >> 1) * 4096 + (tid & 1) * 16 + t * 32;
#pragma unroll
            for (int j = 0; j < 4; j++) bv[j] = *(const float4*)(p + 4 * j);
        } else {
            const int brow = tid >> 5;
            const int bcol = (tid & 31) * 4;
            const float* p = Bbase + (size_t)(t * 32 + brow) * LDBN + bcol;
#pragma unroll
            for (int j = 0; j < 4; j++) bv[j] = *(const float4*)(p + (size_t)(8 * j) * LDBN);
        }
    };
    auto stsA = [&]() {
#pragma unroll
        for (int j = 0; j < 4; j++) {
            As[akh + 4 * j + 0][arow] = tf32r(av[j].x);
            As[akh + 4 * j + 1][arow] = tf32r(av[j].y);
            As[akh + 4 * j + 2][arow] = tf32r(av[j].z);
            As[akh + 4 * j + 3][arow] = tf32r(av[j].w);
        }
    };
    auto stsB = [&]() {
        if constexpr (BT) {
            const int nrow = tid >> 1;
            const int kh = (tid & 1) * 16;
#pragma unroll
            for (int j = 0; j < 4; j++) {
                Bs[kh + 4 * j + 0][nrow] = tf32r(bv[j].x);
                Bs[kh + 4 * j + 1][nrow] = tf32r(bv[j].y);
                Bs[kh + 4 * j + 2][nrow] = tf32r(bv[j].z);
                Bs[kh + 4 * j + 3][nrow] = tf32r(bv[j].w);
            }
        } else {
            const int brow = tid >> 5;
            const int bcol = (tid & 31) * 4;
#pragma unroll
            for (int j = 0; j < 4; j++) {
                uint32_t* p = &Bs[brow + 8 * j][bcol];
                p[0] = tf32r(bv[j].x); p[1] = tf32r(bv[j].y);
                p[2] = tf32r(bv[j].z); p[3] = tf32r(bv[j].w);
            }
        }
    };

    float c[2][8][4];
#pragma unroll
    for (int mi = 0; mi < 2; mi++)
#pragma unroll
        for (int ni = 0; ni < 8; ni++)
#pragma unroll
            for (int r = 0; r < 4; r++) c[mi][ni][r] = 0.f;

    loadA(0); loadB(0);
    for (int t = 0; t < NT; t++) {
        stsA(); stsB();
        __syncthreads();
        if (t + 1 < NT) { loadA(t + 1); loadB(t + 1); }

#pragma unroll
        for (int kk = 0; kk < 4; kk++) {
            const int kb = kk * 8;
            uint32_t a[2][4];
#pragma unroll
            for (int mi = 0; mi < 2; mi++) {
                a[mi][0] = As[kb + tg][wm + 16 * mi + g];
                a[mi][1] = As[kb + tg][wm + 16 * mi + g + 8];
                a[mi][2] = As[kb + tg + 4][wm + 16 * mi + g];
                a[mi][3] = As[kb + tg + 4][wm + 16 * mi + g + 8];
            }
#pragma unroll
            for (int ni = 0; ni < 8; ni++) {
                uint32_t b0 = Bs[kb + tg][wn + 8 * ni + g];
                uint32_t b1 = Bs[kb + tg + 4][wn + 8 * ni + g];
#pragma unroll
                for (int mi = 0; mi < 2; mi++)
                    MMA_TF32(c[mi][ni], a[mi][0], a[mi][1], a[mi][2], a[mi][3], b0, b1);
            }
        }
        __syncthreads();
    }

#pragma unroll
    for (int mi = 0; mi < 2; mi++) {
        const int row = m0 + wm + 16 * mi + g;
#pragma unroll
        for (int ni = 0; ni < 8; ni++) {
            const int col = n0 + wn + 8 * ni + 2 * tg;
            float2 lo = make_float2(c[mi][ni][0], c[mi][ni][1]);
            float2 hi = make_float2(c[mi][ni][2], c[mi][ni][3]);
            if constexpr (MODE == MODE_Q) {
                *(float2*)(g_q + (size_t)row * 1024 + col) = lo;
                *(float2*)(g_q + (size_t)(row + 8) * 1024 + col) = hi;
            } else if constexpr (MODE == MODE_KV) {
                float* base = (n0 < 1024) ? g_k : g_v;
                int cc = (n0 < 1024) ? col : col - 1024;
                *(float2*)(base + (size_t)row * 1024 + cc) = lo;
                *(float2*)(base + (size_t)(row + 8) * 1024 + cc) = hi;
            } else {
                float2 bb = *(const float2*)(bias + col);
                *(float2*)(Cout + (size_t)row * 1024 + col) =
                    make_float2(lo.x + bb.x, lo.y + bb.y);
                *(float2*)(Cout + (size_t)(row + 8) * 1024 + col) =
                    make_float2(hi.x + bb.x, hi.y + bb.y);
            }
        }
    }
}

// conv_w (o, d, r) -> (o, r*1024 + d)
__global__ void convw_kernel(const float* __restrict__ in, float* __restrict__ out)
{
    int i = blockIdx.x * 256 + threadIdx.x;
    int o = i >> 12, rem = i & 4095, d = rem >> 2, r = rem & 3;
    out[(size_t)o * 4096 + r * 1024 + d] = in[i];
}

// ---------------------------------------------------------------------------
// Tensor-core flash attention with inline relative-position term.
// Block: 64 queries x one (b,h). 8 warps (4 m-bands x 2 n-halves).
// Per 64-key tile: S1 = Q@K^T (mma), S2 = Q@PEwin^T (mma) scatter-added with
// the shift j = u + i - 63, SIMT online softmax, PV via mma.
// ---------------------------------------------------------------------------
#define ATT_SMEM ((64*132 + 64*136 + 128*132 + 64*68 + 64*68 + 128) * 4)

__global__ void __launch_bounds__(256, 1) attn_kernel(const float* __restrict__ pe)
{
    extern __shared__ float smf[];
    uint32_t* Qs  = (uint32_t*)smf;          // [64][132] tf32, Q prescaled
    uint32_t* KVs = Qs + 64 * 132;           // K: [64][132] / V: [64][136]
    uint32_t* PEs = KVs + 64 * 136;          // [128][132] (127 rows used)
    float*    Ss  = (float*)(PEs + 128 * 132);   // [64][68] scores
    uint32_t* Ps  = (uint32_t*)(Ss + 64 * 68);   // [64][68] probs (tf32)
    float*    corr_s = (float*)(Ps + 64 * 68);   // [64]
    float*    invl_s = corr_s + 64;              // [64]

    const int tid = threadIdx.x;
    const int wid = tid >> 5, lid = tid & 31;
    const int g = lid >> 2, tg = lid & 3;
    const int wm = (wid & 3) * 16;           // warp m-band
    const int half = wid >> 2;               // warp n-half
    const int tx = tid & 15, ty = tid >> 4;  // softmax layout
    const int qx = 15 - (int)blockIdx.x;     // heavy blocks first
    const int q0 = qx * 64;
    const int bh = blockIdx.y;
    const int b = bh >> 3, h = bh & 7;

    const int ldr = tid >> 2;                // tile loader: 4 threads/row
    const int ldc = (tid & 3) * 32;

    // Q tile (prescaled, tf32)
    {
        const float* src = g_q + ((size_t)(b * T_ + q0 + ldr)) * 1024 + h * 128 + ldc;
        uint32_t* dst = Qs + ldr * 132 + ldc;
#pragma unroll
        for (int i = 0; i < 8; i++) {
            float4 v = *(const float4*)(src + 4 * i);
            dst[4 * i + 0] = tf32r(v.x * SCALE_);
            dst[4 * i + 1] = tf32r(v.y * SCALE_);
            dst[4 * i + 2] = tf32r(v.z * SCALE_);
            dst[4 * i + 3] = tf32r(v.w * SCALE_);
        }
    }

    float o[8][4];
#pragma unroll
    for (int d = 0; d < 8; d++)
#pragma unroll
        for (int r = 0; r < 4; r++) o[d][r] = 0.f;
    float m_run[4], l_run[4];
#pragma unroll
    for (int i = 0; i < 4; i++) { m_run[i] = -INFINITY; l_run[i] = 0.f; }

    const int n_tiles = qx + 21;
    const float* peh = pe + (size_t)h * KV_ * 128;

    for (int t = 0; t < n_tiles; t++) {
        const int m0 = t * 64;
        const int r0 = m0 - q0 + 960;
        __syncthreads();  // A: previous tile's PV done; buffers free

        // K tile
        {
            const float* src = g_k + ((size_t)(b * KV_ + m0 + ldr)) * 1024 + h * 128 + ldc;
            uint32_t* dst = KVs + ldr * 132 + ldc;
#pragma unroll
            for (int i = 0; i < 8; i++) {
                float4 v = *(const float4*)(src + 4 * i);
                dst[4 * i + 0] = tf32r(v.x); dst[4 * i + 1] = tf32r(v.y);
                dst[4 * i + 2] = tf32r(v.z); dst[4 * i + 3] = tf32r(v.w);
            }
        }
        // PE window (127 rows; clamp r>=2304 to row 0 — only masked slots use it)
        {
            int u = tid >> 1;
            if (u < 127) {
                int r = r0 + u;
                if (r >= KV_) r = 0;
                int c0 = (tid & 1) * 64;
                const float* src = peh + (size_t)r * 128 + c0;
                uint32_t* dst = PEs + u * 132 + c0;
#pragma unroll
                for (int i = 0; i < 16; i++) {
                    float4 v = *(const float4*)(src + 4 * i);
                    dst[4 * i + 0] = tf32r(v.x); dst[4 * i + 1] = tf32r(v.y);
                    dst[4 * i + 2] = tf32r(v.z); dst[4 * i + 3] = tf32r(v.w);
                }
            }
        }
        __syncthreads();  // B: tiles loaded

        // S1 = Q @ K^T  (warp: 16 rows x 32 cols)
        {
            float c1[4][4];
#pragma unroll
            for (int nf = 0; nf < 4; nf++)
#pragma unroll
                for (int r = 0; r < 4; r++) c1[nf][r] = 0.f;
#pragma unroll
            for (int kb8 = 0; kb8 < 16; kb8++) {
                const int kb = kb8 * 8;
                uint32_t a0 = Qs[(wm + g) * 132 + kb + tg];
                uint32_t a1 = Qs[(wm + g + 8) * 132 + kb + tg];
                uint32_t a2 = Qs[(wm + g) * 132 + kb + tg + 4];
                uint32_t a3 = Qs[(wm + g + 8) * 132 + kb + tg + 4];
#pragma unroll
                for (int nf = 0; nf < 4; nf++) {
                    uint32_t b0 = KVs[(half * 32 + nf * 8 + g) * 132 + kb + tg];
                    uint32_t b1 = KVs[(half * 32 + nf * 8 + g) * 132 + kb + tg + 4];
                    MMA_TF32(c1[nf], a0, a1, a2, a3, b0, b1);
                }
            }
#pragma unroll
            for (int nf = 0; nf < 4; nf++) {
                const int col = half * 32 + nf * 8 + 2 * tg;
                *(float2*)(Ss + (wm + g) * 68 + col) = make_float2(c1[nf][0], c1[nf][1]);
                *(float2*)(Ss + (wm + g + 8) * 68 + col) = make_float2(c1[nf][2], c1[nf][3]);
            }
        }
        __syncthreads();  // C: S1 written

        // S2 = Q @ PEwin^T (warp: 16 rows x 64 u-cols), scatter-add shifted
        {
            float c2[8][4];
#pragma unroll
            for (int uf = 0; uf < 8; uf++)
#pragma unroll
                for (int r = 0; r < 4; r++) c2[uf][r] = 0.f;
#pragma unroll
            for (int kb8 = 0; kb8 < 16; kb8++) {
                const int kb = kb8 * 8;
                uint32_t a0 = Qs[(wm + g) * 132 + kb + tg];
                uint32_t a1 = Qs[(wm + g + 8) * 132 + kb + tg];
                uint32_t a2 = Qs[(wm + g) * 132 + kb + tg + 4];
                uint32_t a3 = Qs[(wm + g + 8) * 132 + kb + tg + 4];
#pragma unroll
                for (int uf = 0; uf < 8; uf++) {
                    uint32_t b0 = PEs[(half * 64 + uf * 8 + g) * 132 + kb + tg];
                    uint32_t b1 = PEs[(half * 64 + uf * 8 + g) * 132 + kb + tg + 4];
                    MMA_TF32(c2[uf], a0, a1, a2, a3, b0, b1);
                }
            }
            const int i0 = wm + g, i1 = wm + g + 8;
#pragma unroll
            for (int uf = 0; uf < 8; uf++) {
                const int ub = half * 64 + uf * 8 + 2 * tg;
                int j;
                j = ub + i0 - 63;     if ((unsigned)j < 64u) Ss[i0 * 68 + j] += c2[uf][0];
                j = ub + 1 + i0 - 63; if ((unsigned)j < 64u) Ss[i0 * 68 + j] += c2[uf][1];
                j = ub + i1 - 63;     if ((unsigned)j < 64u) Ss[i1 * 68 + j] += c2[uf][2];
                j = ub + 1 + i1 - 63; if ((unsigned)j < 64u) Ss[i1 * 68 + j] += c2[uf][3];
            }
        }
        // V tile (K no longer needed)
        {
            const float* src = g_v + ((size_t)(b * KV_ + m0 + ldr)) * 1024 + h * 128 + ldc;
            uint32_t* dst = KVs + ldr * 136 + ldc;
#pragma unroll
            for (int i = 0; i < 8; i++) {
                float4 v = *(const float4*)(src + 4 * i);
                dst[4 * i + 0] = tf32r(v.x); dst[4 * i + 1] = tf32r(v.y);
                dst[4 * i + 2] = tf32r(v.z); dst[4 * i + 3] = tf32r(v.w);
            }
        }
        __syncthreads();  // D: scores complete, V loaded

        // SIMT online softmax (rows ty+16ii, cols tx+16jj)
#pragma unroll
        for (int ii = 0; ii < 4; ii++) {
            const int i = ty + 16 * ii;
            const int qg = q0 + i;
            float s0 = Ss[i * 68 + tx];
            float s1 = Ss[i * 68 + tx + 16];
            float s2 = Ss[i * 68 + tx + 32];
            float s3 = Ss[i * 68 + tx + 48];
            if (m0 + tx      > qg + TOTMEM_) s0 = -INFINITY;
            if (m0 + tx + 16 > qg + TOTMEM_) s1 = -INFINITY;
            if (m0 + tx + 32 > qg + TOTMEM_) s2 = -INFINITY;
            if (m0 + tx + 48 > qg + TOTMEM_) s3 = -INFINITY;

            float mx = fmaxf(fmaxf(s0, s1), fmaxf(s2, s3));
            mx = fmaxf(mx, __shfl_xor_sync(0xffffffffu, mx, 1, 16));
            mx = fmaxf(mx, __shfl_xor_sync(0xffffffffu, mx, 2, 16));
            mx = fmaxf(mx, __shfl_xor_sync(0xffffffffu, mx, 4, 16));
            mx = fmaxf(mx, __shfl_xor_sync(0xffffffffu, mx, 8, 16));
            float m_new = fmaxf(m_run[ii], mx);
            float corrv = __expf(m_run[ii] - m_new);
            float p0 = __expf(s0 - m_new);
            float p1 = __expf(s1 - m_new);
            float p2 = __expf(s2 - m_new);
            float p3 = __expf(s3 - m_new);
            float sum = p0 + p1 + p2 + p3;
            sum += __shfl_xor_sync(0xffffffffu, sum, 1, 16);
            sum += __shfl_xor_sync(0xffffffffu, sum, 2, 16);
            sum += __shfl_xor_sync(0xffffffffu, sum, 4, 16);
            sum += __shfl_xor_sync(0xffffffffu, sum, 8, 16);
            l_run[ii] = l_run[ii] * corrv + sum;
            m_run[ii] = m_new;
            Ps[i * 68 + tx]      = tf32r(p0);
            Ps[i * 68 + tx + 16] = tf32r(p1);
            Ps[i * 68 + tx + 32] = tf32r(p2);
            Ps[i * 68 + tx + 48] = tf32r(p3);
            if (tx == 0) corr_s[i] = corrv;
        }
        __syncthreads();  // E: P, corr ready

        // PV: O = O*corr + P @ V  (warp: 16 rows x 64 d-cols)
        {
            const float cr0 = corr_s[wm + g];
            const float cr8 = corr_s[wm + g + 8];
#pragma unroll
            for (int df = 0; df < 8; df++) {
                o[df][0] *= cr0; o[df][1] *= cr0;
                o[df][2] *= cr8; o[df][3] *= cr8;
            }
#pragma unroll
            for (int kb8 = 0; kb8 < 8; kb8++) {
                const int kb = kb8 * 8;
                uint32_t a0 = Ps[(wm + g) * 68 + kb + tg];
                uint32_t a1 = Ps[(wm + g + 8) * 68 + kb + tg];
                uint32_t a2 = Ps[(wm + g) * 68 + kb + tg + 4];
                uint32_t a3 = Ps[(wm + g + 8) * 68 + kb + tg + 4];
#pragma unroll
                for (int df = 0; df < 8; df++) {
                    uint32_t b0 = KVs[(kb + tg) * 136 + half * 64 + df * 8 + g];
                    uint32_t b1 = KVs[(kb + tg + 4) * 136 + half * 64 + df * 8 + g];
                    MMA_TF32(o[df], a0, a1, a2, a3, b0, b1);
                }
            }
        }
    }

    // Finalize: normalize and write g_attn
    if (tx == 0) {
#pragma unroll
        for (int ii = 0; ii < 4; ii++)
            invl_s[ty + 16 * ii] = 1.f / l_run[ii];
    }
    __syncthreads();
    const float il0 = invl_s[wm + g];
    const float il8 = invl_s[wm + g + 8];
    const int row0 = q0 + wm + g;
#pragma unroll
    for (int df = 0; df < 8; df++) {
        const int col = h * 128 + half * 64 + df * 8 + 2 * tg;
        *(float2*)(g_attn + ((size_t)(b * T_ + row0)) * 1024 + col) =
            make_float2(o[df][0] * il0, o[df][1] * il0);
        *(float2*)(g_attn + ((size_t)(b * T_ + row0 + 8)) * 1024 + col) =
            make_float2(o[df][2] * il8, o[df][3] * il8);
    }
}

// ---------------------------------------------------------------------------
// Tail: new_mem = x (copy), aux_loss = 0
// ---------------------------------------------------------------------------
__global__ void tail_kernel(const float* __restrict__ x, float* __restrict__ out)
{
    const size_t n4 = (size_t)B_ * T_ * E_ / 4;
    float4* dst = (float4*)(out + (size_t)B_ * T_ * E_);
    const float4* src = (const float4*)x;
    size_t i = (size_t)blockIdx.x * blockDim.x + threadIdx.x;
    for (size_t k = i; k < n4; k += (size_t)gridDim.x * blockDim.x) dst[k] = src[k];
    if (i == 0)
        out[(size_t)B_ * T_ * E_ * 2 + (size_t)B_ * CML_ * E_] = 0.f;
}

// ---------------------------------------------------------------------------
extern "C" void kernel_launch(void* const* d_in, const int* in_sizes, int n_in,
                              void* d_out, int out_size)
{
    (void)in_sizes; (void)n_in;
    const float* x      = (const float*)d_in[0];
    const float* mem    = (const float*)d_in[1];
    const float* cmem   = (const float*)d_in[2];
    const float* pe     = (const float*)d_in[3];
    const float* Wq     = (const float*)d_in[5];
    const float* Wkv    = (const float*)d_in[6];
    const float* Wout   = (const float*)d_in[7];
    const float* b_out  = (const float*)d_in[8];
    const float* conv_w = (const float*)d_in[9];
    const float* conv_b = (const float*)d_in[10];

    float* out = (float*)d_out;
    float* out_logits = out;
    float* out_cmem   = out + (size_t)2 * B_ * T_ * E_;

    float* cwt;
    cudaGetSymbolAddress((void**)&cwt, g_cwt);

    cudaFuncSetAttribute(attn_kernel, cudaFuncAttributeMaxDynamicSharedMemorySize,
                         ATT_SMEM);

    convw_kernel<<<16384, 256>>>(conv_w, cwt);

    // q = x @ Wq
    mma_gemm<MODE_Q><<<dim3(8, 32), 256>>>(x, nullptr, nullptr, Wq, nullptr, nullptr);
    // kv = [cmem;mem;x] @ Wkv
    mma_gemm<MODE_KV><<<dim3(16, 72), 256>>>(x, mem, cmem, Wkv, nullptr, nullptr);
    // attention (inline pos term)
    attn_kernel<<<dim3(16, 32), 256, ATT_SMEM>>>(pe);
    // logits = attn_out @ Wout + b_out
    mma_gemm<MODE_OUT><<<dim3(8, 32), 256>>>(nullptr, nullptr, nullptr, Wout, b_out, out_logits);
    // new_cmem = conv(mem)
    mma_gemm<MODE_CMEM><<<dim3(8, 8), 256>>>(nullptr, mem, nullptr, cwt, conv_b, out_cmem);
    // new_mem = x; aux = 0
    tail_kernel<<<1024, 256>>>(x, out);
}

// round 7
// speedup vs baseline: 1.4098x; 1.4098x over previous
#include <cuda_runtime.h>
#include <cuda_bf16.h>
#include <math.h>
#include <stdint.h>

// Problem constants
#define B_ 4
#define T_ 1024
#define E_ 1024
#define H_ 8
#define DH_ 128
#define KV_ 2304
#define CML_ 256
#define MEML_ 1024
#define TOTMEM_ 1280
#define SCALE_ 0.08838834764831845f

// Scratch (device globals — allocation-free rule)
__device__ float g_q[B_ * T_ * E_];      // pre-scaled, tf32-rounded
__device__ float g_k[B_ * KV_ * E_];     // tf32-rounded
__device__ float g_v[B_ * KV_ * E_];     // tf32-rounded
__device__ float g_attn[B_ * T_ * E_];
__device__ float g_pe[H_ * KV_ * DH_];   // tf32-rounded pos_emb
__device__ float g_cwt[1024 * 4096];     // conv_w permuted to (o, r*1024+d)

#define MODE_Q 0
#define MODE_KV 1
#define MODE_OUT 3
#define MODE_CMEM 4

__device__ __forceinline__ uint32_t tf32r(float f) {
    uint32_t r;
    asm("cvt.rna.tf32.f32 %0, %1;" : "=r"(r) : "f"(f));
    return r;
}
__device__ __forceinline__ float tf32f(float f) {
    return __uint_as_float(tf32r(f));
}

#define MMA_TF32(c, a0, a1, a2, a3, b0, b1) \
    asm volatile( \
        "mma.sync.aligned.m16n8k8.row.col.f32.tf32.tf32.f32 " \
        "{%0,%1,%2,%3}, {%4,%5,%6,%7}, {%8,%9}, {%0,%1,%2,%3};" \
        : "+f"((c)[0]), "+f"((c)[1]), "+f"((c)[2]), "+f"((c)[3]) \
        : "r"(a0), "r"(a1), "r"(a2), "r"(a3), "r"(b0), "r"(b1))

__device__ __forceinline__ uint32_t smem_u32(const void* p) {
    uint32_t a;
    asm("{ .reg .u64 t; cvta.to.shared.u64 t, %1; cvt.u32.u64 %0, t; }" : "=r"(a) : "l"(p));
    return a;
}
__device__ __forceinline__ void cpa16(uint32_t dst, const float* src) {
    asm volatile("cp.async.cg.shared.global [%0], [%1], 16;" :: "r"(dst), "l"(src));
}
#define CP_COMMIT() asm volatile("cp.async.commit_group;" ::: "memory")
#define CP_WAIT(n)  asm volatile("cp.async.wait_group %0;" :: "n"(n) : "memory")

// ---------------------------------------------------------------------------
// tf32 mma.sync GEMM: 128x128x32 block tile, 8 warps, warp tile 32x64
// ---------------------------------------------------------------------------
template <int MODE>
__global__ void __launch_bounds__(256) mma_gemm(
    const float* __restrict__ A0, const float* __restrict__ A1,
    const float* __restrict__ A2, const float* __restrict__ Bmat,
    const float* __restrict__ bias, float* __restrict__ Cout)
{
    constexpr int K    = (MODE == MODE_CMEM) ? 4096 : 1024;
    constexpr int LDA  = (MODE == MODE_CMEM) ? 4096 : 1024;
    constexpr int LDBN = (MODE == MODE_KV) ? 2048 : 1024;
    constexpr bool BT  = (MODE == MODE_CMEM);
    constexpr int NT   = K / 32;

    __shared__ uint32_t As[32][132];
    __shared__ uint32_t Bs[32][132];

    const int tid = threadIdx.x;
    const int wid = tid >> 5;
    const int lid = tid & 31;
    const int g   = lid >> 2;
    const int tg  = lid & 3;
    const int m0 = blockIdx.y * 128;
    const int n0 = blockIdx.x * 128;
    const int wm = (wid & 3) * 32;
    const int wn = (wid >> 2) * 64;

    const float* Abase;
    const float* Bbase;
    if constexpr (MODE == MODE_Q) {
        Abase = A0 + (size_t)m0 * 1024;
        Bbase = Bmat + n0;
    } else if constexpr (MODE == MODE_KV) {
        int b = m0 / KV_;
        int j = m0 - b * KV_;
        if (j < CML_)              Abase = A2 + (size_t)(b * CML_ + j) * 1024;
        else if (j < CML_ + MEML_) Abase = A1 + (size_t)(b * MEML_ + (j - CML_)) * 1024;
        else                       Abase = A0 + (size_t)(b * T_ + (j - CML_ - MEML_)) * 1024;
        Bbase = Bmat + n0;
    } else if constexpr (MODE == MODE_OUT) {
        Abase = g_attn + (size_t)m0 * 1024;
        Bbase = Bmat + n0;
    } else { // CMEM
        Abase = A1 + (size_t)m0 * 4096;
        Bbase = Bmat + (size_t)n0 * 4096;
    }

    const int arow = tid >> 1;
    const int akh  = (tid & 1) * 16;
    const float* aPtr = Abase + (size_t)arow * LDA + akh;

    float4 av[4], bv[4];
    auto loadA = [&](int t) {
        const float* p = aPtr + t * 32;
#pragma unroll
        for (int j = 0; j < 4; j++) av[j] = *(const float4*)(p + 4 * j);
    };
    auto loadB = [&](int t) {
        if constexpr (BT) {
            const float* p = Bbase + (size_t)(tid >> 1) * 4096 + (tid & 1) * 16 + t * 32;
#pragma unroll
            for (int j = 0; j < 4; j++) bv[j] = *(const float4*)(p + 4 * j);
        } else {
            const int brow = tid >> 5;
            const int bcol = (tid & 31) * 4;
            const float* p = Bbase + (size_t)(t * 32 + brow) * LDBN + bcol;
#pragma unroll
            for (int j = 0; j < 4; j++) bv[j] = *(const float4*)(p + (size_t)(8 * j) * LDBN);
        }
    };
    auto stsA = [&]() {
#pragma unroll
        for (int j = 0; j < 4; j++) {
            As[akh + 4 * j + 0][arow] = tf32r(av[j].x);
            As[akh + 4 * j + 1][arow] = tf32r(av[j].y);
            As[akh + 4 * j + 2][arow] = tf32r(av[j].z);
            As[akh + 4 * j + 3][arow] = tf32r(av[j].w);
        }
    };
    auto stsB = [&]() {
        if constexpr (BT) {
            const int nrow = tid >> 1;
            const int kh = (tid & 1) * 16;
#pragma unroll
            for (int j = 0; j < 4; j++) {
                Bs[kh + 4 * j + 0][nrow] = tf32r(bv[j].x);
                Bs[kh + 4 * j + 1][nrow] = tf32r(bv[j].y);
                Bs[kh + 4 * j + 2][nrow] = tf32r(bv[j].z);
                Bs[kh + 4 * j + 3][nrow] = tf32r(bv[j].w);
            }
        } else {
            const int brow = tid >> 5;
            const int bcol = (tid & 31) * 4;
#pragma unroll
            for (int j = 0; j < 4; j++) {
                uint32_t* p = &Bs[brow + 8 * j][bcol];
                p[0] = tf32r(bv[j].x); p[1] = tf32r(bv[j].y);
                p[2] = tf32r(bv[j].z); p[3] = tf32r(bv[j].w);
            }
        }
    };

    float c[2][8][4];
#pragma unroll
    for (int mi = 0; mi < 2; mi++)
#pragma unroll
        for (int ni = 0; ni < 8; ni++)
#pragma unroll
            for (int r = 0; r < 4; r++) c[mi][ni][r] = 0.f;

    loadA(0); loadB(0);
    for (int t = 0; t < NT; t++) {
        stsA(); stsB();
        __syncthreads();
        if (t + 1 < NT) { loadA(t + 1); loadB(t + 1); }

#pragma unroll
        for (int kk = 0; kk < 4; kk++) {
            const int kb = kk * 8;
            uint32_t a[2][4];
#pragma unroll
            for (int mi = 0; mi < 2; mi++) {
                a[mi][0] = As[kb + tg][wm + 16 * mi + g];
                a[mi][1] = As[kb + tg][wm + 16 * mi + g + 8];
                a[mi][2] = As[kb + tg + 4][wm + 16 * mi + g];
                a[mi][3] = As[kb + tg + 4][wm + 16 * mi + g + 8];
            }
#pragma unroll
            for (int ni = 0; ni < 8; ni++) {
                uint32_t b0 = Bs[kb + tg][wn + 8 * ni + g];
                uint32_t b1 = Bs[kb + tg + 4][wn + 8 * ni + g];
#pragma unroll
                for (int mi = 0; mi < 2; mi++)
                    MMA_TF32(c[mi][ni], a[mi][0], a[mi][1], a[mi][2], a[mi][3], b0, b1);
            }
        }
        __syncthreads();
    }

#pragma unroll
    for (int mi = 0; mi < 2; mi++) {
        const int row = m0 + wm + 16 * mi + g;
#pragma unroll
        for (int ni = 0; ni < 8; ni++) {
            const int col = n0 + wn + 8 * ni + 2 * tg;
            float2 lo = make_float2(c[mi][ni][0], c[mi][ni][1]);
            float2 hi = make_float2(c[mi][ni][2], c[mi][ni][3]);
            if constexpr (MODE == MODE_Q) {
                // pre-scale + tf32 pre-round for attention consumption
                *(float2*)(g_q + (size_t)row * 1024 + col) =
                    make_float2(tf32f(lo.x * SCALE_), tf32f(lo.y * SCALE_));
                *(float2*)(g_q + (size_t)(row + 8) * 1024 + col) =
                    make_float2(tf32f(hi.x * SCALE_), tf32f(hi.y * SCALE_));
            } else if constexpr (MODE == MODE_KV) {
                float* base = (n0 < 1024) ? g_k : g_v;
                int cc = (n0 < 1024) ? col : col - 1024;
                *(float2*)(base + (size_t)row * 1024 + cc) =
                    make_float2(tf32f(lo.x), tf32f(lo.y));
                *(float2*)(base + (size_t)(row + 8) * 1024 + cc) =
                    make_float2(tf32f(hi.x), tf32f(hi.y));
            } else {
                float2 bb = *(const float2*)(bias + col);
                *(float2*)(Cout + (size_t)row * 1024 + col) =
                    make_float2(lo.x + bb.x, lo.y + bb.y);
                *(float2*)(Cout + (size_t)(row + 8) * 1024 + col) =
                    make_float2(hi.x + bb.x, hi.y + bb.y);
            }
        }
    }
}

// conv_w (o, d, r) -> (o, r*1024 + d)
__global__ void convw_kernel(const float* __restrict__ in, float* __restrict__ out)
{
    int i = blockIdx.x * 256 + threadIdx.x;
    int o = i >> 12, rem = i & 4095, d = rem >> 2, r = rem & 3;
    out[(size_t)o * 4096 + r * 1024 + d] = in[i];
}

// pos_emb -> tf32-rounded copy
__global__ void pe_round_kernel(const float* __restrict__ in, float* __restrict__ out)
{
    int i = blockIdx.x * 256 + threadIdx.x;
    out[i] = tf32f(in[i]);
}

// ---------------------------------------------------------------------------
// Tensor-core flash attention, cp.async pipelined, sliding PE window.
// smem word layout:
//   Qs   [64*132]            @ 0
//   Ks   [2][64*132]         @ 8448
//   Vs   [64*136]            @ 25344
//   PEs  [2][64*132]         @ 34048   (two 64-row pages, slot = page&1)
//   Ss   [64*68]             @ 50944   (scores; probs written in place)
//   corr [64]                @ 55296
//   invl [64]                @ 55360
// total 55424 words = 221696 B
// ---------------------------------------------------------------------------
#define QS_OFF   0
#define KS_OFF   8448
#define KS_SLOT  8448
#define VS_OFF   25344
#define PE_OFF   34048
#define PE_SLOT  8448
#define SS_OFF   50944
#define CORR_OFF 55296
#define INVL_OFF 55360
#define ATT_SMEM (55424 * 4)

__global__ void __launch_bounds__(256, 1) attn_kernel()
{
    extern __shared__ float smf[];
    const uint32_t sb = smem_u32(smf);
    uint32_t* W = (uint32_t*)smf;            // word view
    float*    Ss = smf + SS_OFF;
    uint32_t* Ssu = (uint32_t*)Ss;
    float*    corr_s = smf + CORR_OFF;
    float*    invl_s = smf + INVL_OFF;

    const int tid = threadIdx.x;
    const int wid = tid >> 5, lid = tid & 31;
    const int g = lid >> 2, tg = lid & 3;
    const int wm = (wid & 3) * 16;
    const int half = wid >> 2;
    const int tx = tid & 15, ty = tid >> 4;
    const int qx = 15 - (int)blockIdx.x;
    const int q0 = qx * 64;
    const int bh = blockIdx.y;
    const int b = bh >> 3, h = bh & 7;
    const int n_tiles = qx + 21;

    const int ldr = tid >> 2;        // loader row 0..63
    const int ldc0 = tid & 3;        // loader chunk base (16B chunks)
    const float* peh = g_pe + (size_t)h * KV_ * 128;

    auto issueK = [&](int t) {
        const int m0 = (t < n_tiles) ? t * 64 : 0;
        const float* src = g_k + ((size_t)(b * KV_ + m0 + ldr)) * 1024 + h * 128;
        const uint32_t dst = sb + (KS_OFF + (t & 1) * KS_SLOT + ldr * 132) * 4;
#pragma unroll
        for (int i = 0; i < 8; i++) { int c = ldc0 + 4 * i; cpa16(dst + c * 16, src + c * 4); }
    };
    auto issueV = [&](int t) {
        const int m0 = (t < n_tiles) ? t * 64 : 0;
        const float* src = g_v + ((size_t)(b * KV_ + m0 + ldr)) * 1024 + h * 128;
        const uint32_t dst = sb + (VS_OFF + ldr * 136) * 4;
#pragma unroll
        for (int i = 0; i < 8; i++) { int c = ldc0 + 4 * i; cpa16(dst + c * 16, src + c * 4); }
    };
    auto issuePE = [&](int page) {
        int r = page * 64 + ldr;
        if ((unsigned)r >= (unsigned)KV_) r = 0;   // clamped rows are masked later
        const float* src = peh + (size_t)r * 128;
        const uint32_t dst = sb + (PE_OFF + (page & 1) * PE_SLOT + ldr * 132) * 4;
#pragma unroll
        for (int i = 0; i < 8; i++) { int c = ldc0 + 4 * i; cpa16(dst + c * 16, src + c * 4); }
    };

    // Prologue: G1 = {Q, K0, PE p0, PE p0+1}, G2 = {V0}
    {
        const float* src = g_q + ((size_t)(b * T_ + q0 + ldr)) * 1024 + h * 128;
        const uint32_t dst = sb + (QS_OFF + ldr * 132) * 4;
#pragma unroll
        for (int i = 0; i < 8; i++) { int c = ldc0 + 4 * i; cpa16(dst + c * 16, src + c * 4); }
    }
    const int P0 = 15 - qx;
    issueK(0); issuePE(P0); issuePE(P0 + 1);
    CP_COMMIT();
    issueV(0);
    CP_COMMIT();

    float o[8][4];
#pragma unroll
    for (int d = 0; d < 8; d++)
#pragma unroll
        for (int r = 0; r < 4; r++) o[d][r] = 0.f;
    float m_run[4], l_run[4];
#pragma unroll
    for (int i = 0; i < 4; i++) { m_run[i] = -INFINITY; l_run[i] = 0.f; }

    for (int t = 0; t < n_tiles; t++) {
        const int m0 = t * 64;
        const int P  = t - qx + 15;

        CP_WAIT(1);
        __syncthreads();   // B: K(t), PE window {P,P+1}, (Q at t=0) visible

        // ---- S1 = Q @ K^T ----
        {
            const uint32_t* Kw = W + KS_OFF + (t & 1) * KS_SLOT;
            float c1[4][4];
#pragma unroll
            for (int nf = 0; nf < 4; nf++)
#pragma unroll
                for (int r = 0; r < 4; r++) c1[nf][r] = 0.f;
#pragma unroll
            for (int kb8 = 0; kb8 < 16; kb8++) {
                const int kb = kb8 * 8;
                uint32_t a0 = W[(wm + g) * 132 + kb + tg];
                uint32_t a1 = W[(wm + g + 8) * 132 + kb + tg];
                uint32_t a2 = W[(wm + g) * 132 + kb + tg + 4];
                uint32_t a3 = W[(wm + g + 8) * 132 + kb + tg + 4];
#pragma unroll
                for (int nf = 0; nf < 4; nf++) {
                    uint32_t b0 = Kw[(half * 32 + nf * 8 + g) * 132 + kb + tg];
                    uint32_t b1 = Kw[(half * 32 + nf * 8 + g) * 132 + kb + tg + 4];
                    MMA_TF32(c1[nf], a0, a1, a2, a3, b0, b1);
                }
            }
#pragma unroll
            for (int nf = 0; nf < 4; nf++) {
                const int col = half * 32 + nf * 8 + 2 * tg;
                *(float2*)(Ss + (wm + g) * 68 + col) = make_float2(c1[nf][0], c1[nf][1]);
                *(float2*)(Ss + (wm + g + 8) * 68 + col) = make_float2(c1[nf][2], c1[nf][3]);
            }
        }
        __syncthreads();   // C: S1 stored; K(t) dead for this slot's readers

        issueK(t + 1);
        CP_COMMIT();

        // ---- S2 = Q @ PEwin^T, scatter-add j = u + i - 63 ----
        {
            float c2[8][4];
#pragma unroll
            for (int uf = 0; uf < 8; uf++)
#pragma unroll
                for (int r = 0; r < 4; r++) c2[uf][r] = 0.f;
            const uint32_t* PEb = W + PE_OFF + ((P + half) & 1) * PE_SLOT;
#pragma unroll
            for (int kb8 = 0; kb8 < 16; kb8++) {
                const int kb = kb8 * 8;
                uint32_t a0 = W[(wm + g) * 132 + kb + tg];
                uint32_t a1 = W[(wm + g + 8) * 132 + kb + tg];
                uint32_t a2 = W[(wm + g) * 132 + kb + tg + 4];
                uint32_t a3 = W[(wm + g + 8) * 132 + kb + tg + 4];
#pragma unroll
                for (int uf = 0; uf < 8; uf++) {
                    uint32_t b0 = PEb[(uf * 8 + g) * 132 + kb + tg];
                    uint32_t b1 = PEb[(uf * 8 + g) * 132 + kb + tg + 4];
                    MMA_TF32(c2[uf], a0, a1, a2, a3, b0, b1);
                }
            }
            const int i0 = wm + g, i1 = wm + g + 8;
#pragma unroll
            for (int uf = 0; uf < 8; uf++) {
                const int ub = half * 64 + uf * 8 + 2 * tg;
                int j;
                j = ub + i0 - 63;     if ((unsigned)j < 64u) Ss[i0 * 68 + j] += c2[uf][0];
                j = ub + 1 + i0 - 63; if ((unsigned)j < 64u) Ss[i0 * 68 + j] += c2[uf][1];
                j = ub + i1 - 63;     if ((unsigned)j < 64u) Ss[i1 * 68 + j] += c2[uf][2];
                j = ub + 1 + i1 - 63; if ((unsigned)j < 64u) Ss[i1 * 68 + j] += c2[uf][3];
            }
        }
        __syncthreads();   // D: scores complete; PE slot (P&1) dead

        issuePE(P + 2);    // page for next tile's window, slot (P+2)&1 = P&1
        CP_COMMIT();

        // ---- online softmax (probs in place over Ss) ----
#pragma unroll
        for (int ii = 0; ii < 4; ii++) {
            const int i = ty + 16 * ii;
            const int qg = q0 + i;
            float s0 = Ss[i * 68 + tx];
            float s1 = Ss[i * 68 + tx + 16];
            float s2 = Ss[i * 68 + tx + 32];
            float s3 = Ss[i * 68 + tx + 48];
            if (m0 + tx      > qg + TOTMEM_) s0 = -INFINITY;
            if (m0 + tx + 16 > qg + TOTMEM_) s1 = -INFINITY;
            if (m0 + tx + 32 > qg + TOTMEM_) s2 = -INFINITY;
            if (m0 + tx + 48 > qg + TOTMEM_) s3 = -INFINITY;

            float mx = fmaxf(fmaxf(s0, s1), fmaxf(s2, s3));
            mx = fmaxf(mx, __shfl_xor_sync(0xffffffffu, mx, 1, 16));
            mx = fmaxf(mx, __shfl_xor_sync(0xffffffffu, mx, 2, 16));
            mx = fmaxf(mx, __shfl_xor_sync(0xffffffffu, mx, 4, 16));
            mx = fmaxf(mx, __shfl_xor_sync(0xffffffffu, mx, 8, 16));
            float m_new = fmaxf(m_run[ii], mx);
            float corrv = __expf(m_run[ii] - m_new);
            float p0 = __expf(s0 - m_new);
            float p1 = __expf(s1 - m_new);
            float p2 = __expf(s2 - m_new);
            float p3 = __expf(s3 - m_new);
            float sum = p0 + p1 + p2 + p3;
            sum += __shfl_xor_sync(0xffffffffu, sum, 1, 16);
            sum += __shfl_xor_sync(0xffffffffu, sum, 2, 16);
            sum += __shfl_xor_sync(0xffffffffu, sum, 4, 16);
            sum += __shfl_xor_sync(0xffffffffu, sum, 8, 16);
            l_run[ii] = l_run[ii] * corrv + sum;
            m_run[ii] = m_new;
            Ssu[i * 68 + tx]      = tf32r(p0);
            Ssu[i * 68 + tx + 16] = tf32r(p1);
            Ssu[i * 68 + tx + 32] = tf32r(p2);
            Ssu[i * 68 + tx + 48] = tf32r(p3);
            if (tx == 0) corr_s[i] = corrv;
        }

        CP_WAIT(2);        // V(t) landed (issued end of previous tile)
        __syncthreads();   // E: probs + corr + V visible

        // ---- PV: O = O*corr + P @ V ----
        {
            const uint32_t* Vw = W + VS_OFF;
            const float cr0 = corr_s[wm + g];
            const float cr8 = corr_s[wm + g + 8];
#pragma unroll
            for (int df = 0; df < 8; df++) {
                o[df][0] *= cr0; o[df][1] *= cr0;
                o[df][2] *= cr8; o[df][3] *= cr8;
            }
#pragma unroll
            for (int kb8 = 0; kb8 < 8; kb8++) {
                const int kb = kb8 * 8;
                uint32_t a0 = Ssu[(wm + g) * 68 + kb + tg];
                uint32_t a1 = Ssu[(wm + g + 8) * 68 + kb + tg];
                uint32_t a2 = Ssu[(wm + g) * 68 + kb + tg + 4];
                uint32_t a3 = Ssu[(wm + g + 8) * 68 + kb + tg + 4];
#pragma unroll
                for (int df = 0; df < 8; df++) {
                    uint32_t b0 = Vw[(kb + tg) * 136 + half * 64 + df * 8 + g];
                    uint32_t b1 = Vw[(kb + tg + 4) * 136 + half * 64 + df * 8 + g];
                    MMA_TF32(o[df], a0, a1, a2, a3, b0, b1);
                }
            }
        }
        __syncthreads();   // A: PV done — V buffer and Ss reusable

        issueV(t + 1);
        CP_COMMIT();
    }

    CP_WAIT(0);
    // Finalize
    if (tx == 0) {
#pragma unroll
        for (int ii = 0; ii < 4; ii++)
            invl_s[ty + 16 * ii] = 1.f / l_run[ii];
    }
    __syncthreads();
    const float il0 = invl_s[wm + g];
    const float il8 = invl_s[wm + g + 8];
    const int row0 = q0 + wm + g;
#pragma unroll
    for (int df = 0; df < 8; df++) {
        const int col = h * 128 + half * 64 + df * 8 + 2 * tg;
        *(float2*)(g_attn + ((size_t)(b * T_ + row0)) * 1024 + col) =
            make_float2(o[df][0] * il0, o[df][1] * il0);
        *(float2*)(g_attn + ((size_t)(b * T_ + row0 + 8)) * 1024 + col) =
            make_float2(o[df][2] * il8, o[df][3] * il8);
    }
}

// ---------------------------------------------------------------------------
// Tail: new_mem = x (copy), aux_loss = 0
// ---------------------------------------------------------------------------
__global__ void tail_kernel(const float* __restrict__ x, float* __restrict__ out)
{
    const size_t n4 = (size_t)B_ * T_ * E_ / 4;
    float4* dst = (float4*)(out + (size_t)B_ * T_ * E_);
    const float4* src = (const float4*)x;
    size_t i = (size_t)blockIdx.x * blockDim.x + threadIdx.x;
    for (size_t k = i; k < n4; k += (size_t)gridDim.x * blockDim.x) dst[k] = src[k];
    if (i == 0)
        out[(size_t)B_ * T_ * E_ * 2 + (size_t)B_ * CML_ * E_] = 0.f;
}

// ---------------------------------------------------------------------------
extern "C" void kernel_launch(void* const* d_in, const int* in_sizes, int n_in,
                              void* d_out, int out_size)
{
    (void)in_sizes; (void)n_in;
    const float* x      = (const float*)d_in[0];
    const float* mem    = (const float*)d_in[1];
    const float* cmem   = (const float*)d_in[2];
    const float* pe     = (const float*)d_in[3];
    const float* Wq     = (const float*)d_in[5];
    const float* Wkv    = (const float*)d_in[6];
    const float* Wout   = (const float*)d_in[7];
    const float* b_out  = (const float*)d_in[8];
    const float* conv_w = (const float*)d_in[9];
    const float* conv_b = (const float*)d_in[10];

    float* out = (float*)d_out;
    float* out_logits = out;
    float* out_cmem   = out + (size_t)2 * B_ * T_ * E_;

    float *cwt, *gpe;
    cudaGetSymbolAddress((void**)&cwt, g_cwt);
    cudaGetSymbolAddress((void**)&gpe, g_pe);

    cudaFuncSetAttribute(attn_kernel, cudaFuncAttributeMaxDynamicSharedMemorySize,
                         ATT_SMEM);

    convw_kernel<<<16384, 256>>>(conv_w, cwt);
    pe_round_kernel<<<H_ * KV_ * DH_ / 256, 256>>>(pe, gpe);

    // q = x @ Wq  (epilogue: *SCALE, tf32 round)
    mma_gemm<MODE_Q><<<dim3(8, 32), 256>>>(x, nullptr, nullptr, Wq, nullptr, nullptr);
    // kv = [cmem;mem;x] @ Wkv  (epilogue: tf32 round)
    mma_gemm<MODE_KV><<<dim3(16, 72), 256>>>(x, mem, cmem, Wkv, nullptr, nullptr);
    // attention (inline pos term, cp.async pipelined)
    attn_kernel<<<dim3(16, 32), 256, ATT_SMEM>>>();
    // logits = attn_out @ Wout + b_out
    mma_gemm<MODE_OUT><<<dim3(8, 32), 256>>>(nullptr, nullptr, nullptr, Wout, b_out, out_logits);
    // new_cmem = conv(mem)
    mma_gemm<MODE_CMEM><<<dim3(8, 8), 256>>>(nullptr, mem, nullptr, cwt, conv_b, out_cmem);
    // new_mem = x; aux = 0
    tail_kernel<<<1024, 256>>>(x, out);
}

// round 9
// speedup vs baseline: 1.6136x; 1.1445x over previous
#include <cuda_runtime.h>
#include <cuda_bf16.h>
#include <math.h>
#include <stdint.h>

// Problem constants
#define B_ 4
#define T_ 1024
#define E_ 1024
#define H_ 8
#define DH_ 128
#define KV_ 2304
#define CML_ 256
#define MEML_ 1024
#define TOTMEM_ 1280
#define SCALE_ 0.08838834764831845f

// Scratch (device globals — allocation-free rule)
__device__ float g_q[B_ * T_ * E_];      // pre-scaled, tf32-rounded
__device__ float g_k[B_ * KV_ * E_];     // tf32-rounded
__device__ float g_v[B_ * KV_ * E_];     // tf32-rounded
__device__ float g_attn[B_ * T_ * E_];
__device__ float g_pe[H_ * KV_ * DH_];   // tf32-rounded pos_emb
__device__ float g_cwt[1024 * 4096];     // conv_w permuted to (o, r*1024+d)

#define MODE_Q 0
#define MODE_KV 1
#define MODE_OUT 3
#define MODE_CMEM 4

__device__ __forceinline__ uint32_t tf32r(float f) {
    uint32_t r;
    asm("cvt.rna.tf32.f32 %0, %1;" : "=r"(r) : "f"(f));
    return r;
}
__device__ __forceinline__ float tf32f(float f) {
    return __uint_as_float(tf32r(f));
}

#define MMA_TF32(c, a0, a1, a2, a3, b0, b1) \
    asm volatile( \
        "mma.sync.aligned.m16n8k8.row.col.f32.tf32.tf32.f32 " \
        "{%0,%1,%2,%3}, {%4,%5,%6,%7}, {%8,%9}, {%0,%1,%2,%3};" \
        : "+f"((c)[0]), "+f"((c)[1]), "+f"((c)[2]), "+f"((c)[3]) \
        : "r"(a0), "r"(a1), "r"(a2), "r"(a3), "r"(b0), "r"(b1))

__device__ __forceinline__ uint32_t smem_u32(const void* p) {
    uint32_t a;
    asm("{ .reg .u64 t; cvta.to.shared.u64 t, %1; cvt.u32.u64 %0, t; }" : "=r"(a) : "l"(p));
    return a;
}
__device__ __forceinline__ void cpa16(uint32_t dst, const float* src) {
    asm volatile("cp.async.cg.shared.global [%0], [%1], 16;" :: "r"(dst), "l"(src));
}
#define CP_COMMIT() asm volatile("cp.async.commit_group;" ::: "memory")
#define CP_WAIT(n)  asm volatile("cp.async.wait_group %0;" :: "n"(n) : "memory")

// ---------------------------------------------------------------------------
// tf32 mma.sync GEMM: 128x128x32 block tile, 8 warps, warp tile 32x64
// ---------------------------------------------------------------------------
template <int MODE>
__global__ void __launch_bounds__(256) mma_gemm(
    const float* __restrict__ A0, const float* __restrict__ A1,
    const float* __restrict__ A2, const float* __restrict__ Bmat,
    const float* __restrict__ bias, float* __restrict__ Cout)
{
    constexpr int K    = (MODE == MODE_CMEM) ? 4096 : 1024;
    constexpr int LDA  = (MODE == MODE_CMEM) ? 4096 : 1024;
    constexpr int LDBN = (MODE == MODE_KV) ? 2048 : 1024;
    constexpr bool BT  = (MODE == MODE_CMEM);
    constexpr int NT   = K / 32;

    __shared__ uint32_t As[32][132];
    __shared__ uint32_t Bs[32][132];

    const int tid = threadIdx.x;
    const int wid = tid >> 5;
    const int lid = tid & 31;
    const int g   = lid >> 2;
    const int tg  = lid & 3;
    const int m0 = blockIdx.y * 128;
    const int n0 = blockIdx.x * 128;
    const int wm = (wid & 3) * 32;
    const int wn = (wid >> 2) * 64;

    const float* Abase;
    const float* Bbase;
    if constexpr (MODE == MODE_Q) {
        Abase = A0 + (size_t)m0 * 1024;
        Bbase = Bmat + n0;
    } else if constexpr (MODE == MODE_KV) {
        int b = m0 / KV_;
        int j = m0 - b * KV_;
        if (j < CML_)              Abase = A2 + (size_t)(b * CML_ + j) * 1024;
        else if (j < CML_ + MEML_) Abase = A1 + (size_t)(b * MEML_ + (j - CML_)) * 1024;
        else                       Abase = A0 + (size_t)(b * T_ + (j - CML_ - MEML_)) * 1024;
        Bbase = Bmat + n0;
    } else if constexpr (MODE == MODE_OUT) {
        Abase = g_attn + (size_t)m0 * 1024;
        Bbase = Bmat + n0;
    } else { // CMEM
        Abase = A1 + (size_t)m0 * 4096;
        Bbase = Bmat + (size_t)n0 * 4096;
    }

    const int arow = tid >> 1;
    const int akh  = (tid & 1) * 16;
    const float* aPtr = Abase + (size_t)arow * LDA + akh;

    float4 av[4], bv[4];
    auto loadA = [&](int t) {
        const float* p = aPtr + t * 32;
#pragma unroll
        for (int j = 0; j < 4; j++) av[j] = *(const float4*)(p + 4 * j);
    };
    auto loadB = [&](int t) {
        if constexpr (BT) {
            const float* p = Bbase + (size_t)(tid >> 1) * 4096 + (tid & 1) * 16 + t * 32;
#pragma unroll
            for (int j = 0; j < 4; j++) bv[j] = *(const float4*)(p + 4 * j);
        } else {
            const int brow = tid >> 5;
            const int bcol = (tid & 31) * 4;
            const float* p = Bbase + (size_t)(t * 32 + brow) * LDBN + bcol;
#pragma unroll
            for (int j = 0; j < 4; j++) bv[j] = *(const float4*)(p + (size_t)(8 * j) * LDBN);
        }
    };
    auto stsA = [&]() {
#pragma unroll
        for (int j = 0; j < 4; j++) {
            As[akh + 4 * j + 0][arow] = tf32r(av[j].x);
            As[akh + 4 * j + 1][arow] = tf32r(av[j].y);
            As[akh + 4 * j + 2][arow] = tf32r(av[j].z);
            As[akh + 4 * j + 3][arow] = tf32r(av[j].w);
        }
    };
    auto stsB = [&]() {
        if constexpr (BT) {
            const int nrow = tid >> 1;
            const int kh = (tid & 1) * 16;
#pragma unroll
            for (int j = 0; j < 4; j++) {
                Bs[kh + 4 * j + 0][nrow] = tf32r(bv[j].x);
                Bs[kh + 4 * j + 1][nrow] = tf32r(bv[j].y);
                Bs[kh + 4 * j + 2][nrow] = tf32r(bv[j].z);
                Bs[kh + 4 * j + 3][nrow] = tf32r(bv[j].w);
            }
        } else {
            const int brow = tid >> 5;
            const int bcol = (tid & 31) * 4;
#pragma unroll
            for (int j = 0; j < 4; j++) {
                uint32_t* p = &Bs[brow + 8 * j][bcol];
                p[0] = tf32r(bv[j].x); p[1] = tf32r(bv[j].y);
                p[2] = tf32r(bv[j].z); p[3] = tf32r(bv[j].w);
            }
        }
    };

    float c[2][8][4];
#pragma unroll
    for (int mi = 0; mi < 2; mi++)
#pragma unroll
        for (int ni = 0; ni < 8; ni++)
#pragma unroll
            for (int r = 0; r < 4; r++) c[mi][ni][r] = 0.f;

    loadA(0); loadB(0);
    for (int t = 0; t < NT; t++) {
        stsA(); stsB();
        __syncthreads();
        if (t + 1 < NT) { loadA(t + 1); loadB(t + 1); }

#pragma unroll
        for (int kk = 0; kk < 4; kk++) {
            const int kb = kk * 8;
            uint32_t a[2][4];
#pragma unroll
            for (int mi = 0; mi < 2; mi++) {
                a[mi][0] = As[kb + tg][wm + 16 * mi + g];
                a[mi][1] = As[kb + tg][wm + 16 * mi + g + 8];
                a[mi][2] = As[kb + tg + 4][wm + 16 * mi + g];
                a[mi][3] = As[kb + tg + 4][wm + 16 * mi + g + 8];
            }
#pragma unroll
            for (int ni = 0; ni < 8; ni++) {
                uint32_t b0 = Bs[kb + tg][wn + 8 * ni + g];
                uint32_t b1 = Bs[kb + tg + 4][wn + 8 * ni + g];
#pragma unroll
                for (int mi = 0; mi < 2; mi++)
                    MMA_TF32(c[mi][ni], a[mi][0], a[mi][1], a[mi][2], a[mi][3], b0, b1);
            }
        }
        __syncthreads();
    }

#pragma unroll
    for (int mi = 0; mi < 2; mi++) {
        const int row = m0 + wm + 16 * mi + g;
#pragma unroll
        for (int ni = 0; ni < 8; ni++) {
            const int col = n0 + wn + 8 * ni + 2 * tg;
            float2 lo = make_float2(c[mi][ni][0], c[mi][ni][1]);
            float2 hi = make_float2(c[mi][ni][2], c[mi][ni][3]);
            if constexpr (MODE == MODE_Q) {
                *(float2*)(g_q + (size_t)row * 1024 + col) =
                    make_float2(tf32f(lo.x * SCALE_), tf32f(lo.y * SCALE_));
                *(float2*)(g_q + (size_t)(row + 8) * 1024 + col) =
                    make_float2(tf32f(hi.x * SCALE_), tf32f(hi.y * SCALE_));
            } else if constexpr (MODE == MODE_KV) {
                float* base = (n0 < 1024) ? g_k : g_v;
                int cc = (n0 < 1024) ? col : col - 1024;
                *(float2*)(base + (size_t)row * 1024 + cc) =
                    make_float2(tf32f(lo.x), tf32f(lo.y));
                *(float2*)(base + (size_t)(row + 8) * 1024 + cc) =
                    make_float2(tf32f(hi.x), tf32f(hi.y));
            } else {
                float2 bb = *(const float2*)(bias + col);
                *(float2*)(Cout + (size_t)row * 1024 + col) =
                    make_float2(lo.x + bb.x, lo.y + bb.y);
                *(float2*)(Cout + (size_t)(row + 8) * 1024 + col) =
                    make_float2(hi.x + bb.x, hi.y + bb.y);
            }
        }
    }
}

// conv_w (o, d, r) -> (o, r*1024 + d)
__global__ void convw_kernel(const float* __restrict__ in, float* __restrict__ out)
{
    int i = blockIdx.x * 256 + threadIdx.x;
    int o = i >> 12, rem = i & 4095, d = rem >> 2, r = rem & 3;
    out[(size_t)o * 4096 + r * 1024 + d] = in[i];
}

// pos_emb -> tf32-rounded copy
__global__ void pe_round_kernel(const float* __restrict__ in, float* __restrict__ out)
{
    int i = blockIdx.x * 256 + threadIdx.x;
    out[i] = tf32f(in[i]);
}

// ---------------------------------------------------------------------------
// Tensor-core flash attention v3:
//  - Q mma fragments resident in registers (loaded once per CTA)
//  - S2 = Q@PE computed once per 64-row PE page, cached across tiles
//  - pos term folded into softmax read (u = 63 + j - i)
// smem words:
//   Ks[2][64*132] @ 0        PEs[2][64*132] @ 16896   Vs[64*136] @ 33792
//   Ss[64*68] @ 42496        S2pg[2][64*68] @ 46848   corr @ 55552  invl @ 55616
// total 55680 w = 222720 B
// ---------------------------------------------------------------------------
#define KS_OFF   0
#define PE_OFF   16896
#define VS_OFF   33792
#define SS_OFF   42496
#define S2_OFF   46848
#define CORR_OFF 55552
#define INVL_OFF 55616
#define ATT_SMEM (55680 * 4)

__global__ void __launch_bounds__(256, 1) attn_kernel()
{
    extern __shared__ float smf[];
    const uint32_t sb = smem_u32(smf);
    uint32_t* W = (uint32_t*)smf;
    float*    Ss = smf + SS_OFF;
    uint32_t* Ssu = (uint32_t*)Ss;
    float*    corr_s = smf + CORR_OFF;
    float*    invl_s = smf + INVL_OFF;

    const int tid = threadIdx.x;
    const int wid = tid >> 5, lid = tid & 31;
    const int g = lid >> 2, tg = lid & 3;
    const int wm = (wid & 3) * 16;
    const int half = wid >> 2;
    const int tx = tid & 15, ty = tid >> 4;
    const int qx = 15 - (int)blockIdx.x;
    const int q0 = qx * 64;
    const int bh = blockIdx.y;
    const int b = bh >> 3, h = bh & 7;
    const int n_tiles = qx + 21;
    const int P0 = 15 - qx;

    const int ldr = tid >> 2;
    const int ldc0 = tid & 3;
    const float* peh = g_pe + (size_t)h * KV_ * 128;

    auto issueK = [&](int t) {
        const int m0 = (t < n_tiles) ? t * 64 : 0;
        const float* src = g_k + ((size_t)(b * KV_ + m0 + ldr)) * 1024 + h * 128;
        const uint32_t dst = sb + (KS_OFF + (t & 1) * 8448 + ldr * 132) * 4;
#pragma unroll
        for (int i = 0; i < 8; i++) { int c = ldc0 + 4 * i; cpa16(dst + c * 16, src + c * 4); }
    };
    auto issueV = [&](int t) {
        const int m0 = (t < n_tiles) ? t * 64 : 0;
        const float* src = g_v + ((size_t)(b * KV_ + m0 + ldr)) * 1024 + h * 128;
        const uint32_t dst = sb + (VS_OFF + ldr * 136) * 4;
#pragma unroll
        for (int i = 0; i < 8; i++) { int c = ldc0 + 4 * i; cpa16(dst + c * 16, src + c * 4); }
    };
    auto issuePE = [&](int page) {
        int r = page * 64 + ldr;
        if ((unsigned)r >= (unsigned)KV_) r = 0;   // clamped rows feed only masked slots
        const float* src = peh + (size_t)r * 128;
        const uint32_t dst = sb + (PE_OFF + (page & 1) * 8448 + ldr * 132) * 4;
#pragma unroll
        for (int i = 0; i < 8; i++) { int c = ldc0 + 4 * i; cpa16(dst + c * 16, src + c * 4); }
    };

    // Prologue loads: G1 = {K0, PE P0, PE P0+1}, G2 = {V0}
    issueK(0); issuePE(P0); issuePE(P0 + 1);
    CP_COMMIT();
    issueV(0);
    CP_COMMIT();

    // Q fragments -> registers (g_q is pre-scaled + tf32-rounded)
    uint32_t qf[16][4];
    {
        const float* q0p = g_q + ((size_t)(b * T_ + q0 + wm + g)) * 1024 + h * 128;
        const float* q8p = q0p + 8 * 1024;
#pragma unroll
        for (int kb8 = 0; kb8 < 16; kb8++) {
            const int c = kb8 * 8 + tg;
            qf[kb8][0] = __float_as_uint(q0p[c]);
            qf[kb8][1] = __float_as_uint(q8p[c]);
            qf[kb8][2] = __float_as_uint(q0p[c + 4]);
            qf[kb8][3] = __float_as_uint(q8p[c + 4]);
        }
    }

    float o[8][4];
#pragma unroll
    for (int d = 0; d < 8; d++)
#pragma unroll
        for (int r = 0; r < 4; r++) o[d][r] = 0.f;
    float m_run[4], l_run[4];
#pragma unroll
    for (int i = 0; i < 4; i++) { m_run[i] = -INFINITY; l_run[i] = 0.f; }

    // S2 page GEMM: out[wm..wm+15][half*32..+32] = Q @ PEpage^T
    auto s2page = [&](int page) {
        const uint32_t* PEb = W + PE_OFF + (page & 1) * 8448;
        float* outp = smf + S2_OFF + (page & 1) * 4352;
        float c2[4][4];
#pragma unroll
        for (int vf = 0; vf < 4; vf++)
#pragma unroll
            for (int r = 0; r < 4; r++) c2[vf][r] = 0.f;
#pragma unroll
        for (int kb8 = 0; kb8 < 16; kb8++) {
            const int kb = kb8 * 8;
#pragma unroll
            for (int vf = 0; vf < 4; vf++) {
                const int n = half * 32 + vf * 8 + g;
                uint32_t b0 = PEb[n * 132 + kb + tg];
                uint32_t b1 = PEb[n * 132 + kb + tg + 4];
                MMA_TF32(c2[vf], qf[kb8][0], qf[kb8][1], qf[kb8][2], qf[kb8][3], b0, b1);
            }
        }
#pragma unroll
        for (int vf = 0; vf < 4; vf++) {
            const int col = half * 32 + vf * 8 + 2 * tg;
            *(float2*)(outp + (wm + g) * 68 + col) = make_float2(c2[vf][0], c2[vf][1]);
            *(float2*)(outp + (wm + g + 8) * 68 + col) = make_float2(c2[vf][2], c2[vf][3]);
        }
    };

    // Prologue compute: S2 for page P0 (needs G1)
    CP_WAIT(1);
    __syncthreads();
    s2page(P0);

    for (int t = 0; t < n_tiles; t++) {
        const int m0 = t * 64;
        const int Pb = t - qx + 15;

        CP_WAIT(1);
        __syncthreads();   // K(t), PE(Pb+1) visible; S2(prologue/t-1) visible

        // ---- S1 = Q @ K^T ----
        {
            const uint32_t* Kw = W + KS_OFF + (t & 1) * 8448;
            float c1[4][4];
#pragma unroll
            for (int nf = 0; nf < 4; nf++)
#pragma unroll
                for (int r = 0; r < 4; r++) c1[nf][r] = 0.f;
#pragma unroll
            for (int kb8 = 0; kb8 < 16; kb8++) {
                const int kb = kb8 * 8;
#pragma unroll
                for (int nf = 0; nf < 4; nf++) {
                    const int n = half * 32 + nf * 8 + g;
                    uint32_t b0 = Kw[n * 132 + kb + tg];
                    uint32_t b1 = Kw[n * 132 + kb + tg + 4];
                    MMA_TF32(c1[nf], qf[kb8][0], qf[kb8][1], qf[kb8][2], qf[kb8][3], b0, b1);
                }
            }
#pragma unroll
            for (int nf = 0; nf < 4; nf++) {
                const int col = half * 32 + nf * 8 + 2 * tg;
                *(float2*)(Ss + (wm + g) * 68 + col) = make_float2(c1[nf][0], c1[nf][1]);
                *(float2*)(Ss + (wm + g + 8) * 68 + col) = make_float2(c1[nf][2], c1[nf][3]);
            }
        }

        // ---- S2 for new page Pb+1 ----
        s2page(Pb + 1);
        __syncthreads();   // Ss + S2 cache written; K(t-1)/PE(Pb) slots dead

        issueK(t + 1); issuePE(Pb + 2);
        CP_COMMIT();

        // ---- softmax: s = S1 + S2cache[u], u = 63 + j - i ----
        {
            const float* S2a = smf + S2_OFF + (Pb & 1) * 4352;        // u < 64
            const float* S2b = smf + S2_OFF + ((Pb + 1) & 1) * 4352;  // u >= 64
#pragma unroll
            for (int ii = 0; ii < 4; ii++) {
                const int i = ty + 16 * ii;
                const int qg = q0 + i;
                float s[4];
#pragma unroll
                for (int jj = 0; jj < 4; jj++) {
                    const int j = tx + 16 * jj;
                    const int u = 63 + j - i;
                    float pv = (u < 64) ? S2a[i * 68 + u] : S2b[i * 68 + u - 64];
                    s[jj] = Ss[i * 68 + j] + pv;
                    if (m0 + j > qg + TOTMEM_) s[jj] = -INFINITY;
                }
                float mx = fmaxf(fmaxf(s[0], s[1]), fmaxf(s[2], s[3]));
                mx = fmaxf(mx, __shfl_xor_sync(0xffffffffu, mx, 1, 16));
                mx = fmaxf(mx, __shfl_xor_sync(0xffffffffu, mx, 2, 16));
                mx = fmaxf(mx, __shfl_xor_sync(0xffffffffu, mx, 4, 16));
                mx = fmaxf(mx, __shfl_xor_sync(0xffffffffu, mx, 8, 16));
                float m_new = fmaxf(m_run[ii], mx);
                float corrv = __expf(m_run[ii] - m_new);
                float p0 = __expf(s[0] - m_new);
                float p1 = __expf(s[1] - m_new);
                float p2 = __expf(s[2] - m_new);
                float p3 = __expf(s[3] - m_new);
                float sum = p0 + p1 + p2 + p3;
                sum += __shfl_xor_sync(0xffffffffu, sum, 1, 16);
                sum += __shfl_xor_sync(0xffffffffu, sum, 2, 16);
                sum += __shfl_xor_sync(0xffffffffu, sum, 4, 16);
                sum += __shfl_xor_sync(0xffffffffu, sum, 8, 16);
                l_run[ii] = l_run[ii] * corrv + sum;
                m_run[ii] = m_new;
                Ssu[i * 68 + tx]      = tf32r(p0);
                Ssu[i * 68 + tx + 16] = tf32r(p1);
                Ssu[i * 68 + tx + 32] = tf32r(p2);
                Ssu[i * 68 + tx + 48] = tf32r(p3);
                if (tx == 0) corr_s[i] = corrv;
            }
        }

        CP_WAIT(1);        // V(t) landed (K(t+1)/PE group may pend)
        __syncthreads();   // probs + corr + V visible

        // ---- PV: O = O*corr + P @ V ----
        {
            const uint32_t* Vw = W + VS_OFF;
            const float cr0 = corr_s[wm + g];
            const float cr8 = corr_s[wm + g + 8];
#pragma unroll
            for (int df = 0; df < 8; df++) {
                o[df][0] *= cr0; o[df][1] *= cr0;
                o[df][2] *= cr8; o[df][3] *= cr8;
            }
#pragma unroll
            for (int kb8 = 0; kb8 < 8; kb8++) {
                const int kb = kb8 * 8;
                uint32_t a0 = Ssu[(wm + g) * 68 + kb + tg];
                uint32_t a1 = Ssu[(wm + g + 8) * 68 + kb + tg];
                uint32_t a2 = Ssu[(wm + g) * 68 + kb + tg + 4];
                uint32_t a3 = Ssu[(wm + g + 8) * 68 + kb + tg + 4];
#pragma unroll
                for (int df = 0; df < 8; df++) {
                    uint32_t b0 = Vw[(kb + tg) * 136 + half * 64 + df * 8 + g];
                    uint32_t b1 = Vw[(kb + tg + 4) * 136 + half * 64 + df * 8 + g];
                    MMA_TF32(o[df], a0, a1, a2, a3, b0, b1);
                }
            }
        }
        __syncthreads();   // PV done — V buffer and Ss reusable

        issueV(t + 1);
        CP_COMMIT();
    }

    CP_WAIT(0);
    if (tx == 0) {
#pragma unroll
        for (int ii = 0; ii < 4; ii++)
            invl_s[ty + 16 * ii] = 1.f / l_run[ii];
    }
    __syncthreads();
    const float il0 = invl_s[wm + g];
    const float il8 = invl_s[wm + g + 8];
    const int row0 = q0 + wm + g;
#pragma unroll
    for (int df = 0; df < 8; df++) {
        const int col = h * 128 + half * 64 + df * 8 + 2 * tg;
        *(float2*)(g_attn + ((size_t)(b * T_ + row0)) * 1024 + col) =
            make_float2(o[df][0] * il0, o[df][1] * il0);
        *(float2*)(g_attn + ((size_t)(b * T_ + row0 + 8)) * 1024 + col) =
            make_float2(o[df][2] * il8, o[df][3] * il8);
    }
}

// ---------------------------------------------------------------------------
// Tail: new_mem = x (copy), aux_loss = 0
// ---------------------------------------------------------------------------
__global__ void tail_kernel(const float* __restrict__ x, float* __restrict__ out)
{
    const size_t n4 = (size_t)B_ * T_ * E_ / 4;
    float4* dst = (float4*)(out + (size_t)B_ * T_ * E_);
    const float4* src = (const float4*)x;
    size_t i = (size_t)blockIdx.x * blockDim.x + threadIdx.x;
    for (size_t k = i; k < n4; k += (size_t)gridDim.x * blockDim.x) dst[k] = src[k];
    if (i == 0)
        out[(size_t)B_ * T_ * E_ * 2 + (size_t)B_ * CML_ * E_] = 0.f;
}

// ---------------------------------------------------------------------------
extern "C" void kernel_launch(void* const* d_in, const int* in_sizes, int n_in,
                              void* d_out, int out_size)
{
    (void)in_sizes; (void)n_in;
    const float* x      = (const float*)d_in[0];
    const float* mem    = (const float*)d_in[1];
    const float* cmem   = (const float*)d_in[2];
    const float* pe     = (const float*)d_in[3];
    const float* Wq     = (const float*)d_in[5];
    const float* Wkv    = (const float*)d_in[6];
    const float* Wout   = (const float*)d_in[7];
    const float* b_out  = (const float*)d_in[8];
    const float* conv_w = (const float*)d_in[9];
    const float* conv_b = (const float*)d_in[10];

    float* out = (float*)d_out;
    float* out_logits = out;
    float* out_cmem   = out + (size_t)2 * B_ * T_ * E_;

    float *cwt, *gpe;
    cudaGetSymbolAddress((void**)&cwt, g_cwt);
    cudaGetSymbolAddress((void**)&gpe, g_pe);

    cudaFuncSetAttribute(attn_kernel, cudaFuncAttributeMaxDynamicSharedMemorySize,
                         ATT_SMEM);

    convw_kernel<<<16384, 256>>>(conv_w, cwt);
    pe_round_kernel<<<H_ * KV_ * DH_ / 256, 256>>>(pe, gpe);

    // q = x @ Wq  (epilogue: *SCALE, tf32 round)
    mma_gemm<MODE_Q><<<dim3(8, 32), 256>>>(x, nullptr, nullptr, Wq, nullptr, nullptr);
    // kv = [cmem;mem;x] @ Wkv  (epilogue: tf32 round)
    mma_gemm<MODE_KV><<<dim3(16, 72), 256>>>(x, mem, cmem, Wkv, nullptr, nullptr);
    // attention (reg-resident Q frags, per-page S2 cache)
    attn_kernel<<<dim3(16, 32), 256, ATT_SMEM>>>();
    // logits = attn_out @ Wout + b_out
    mma_gemm<MODE_OUT><<<dim3(8, 32), 256>>>(nullptr, nullptr, nullptr, Wout, b_out, out_logits);
    // new_cmem = conv(mem)
    mma_gemm<MODE_CMEM><<<dim3(8, 8), 256>>>(nullptr, mem, nullptr, cwt, conv_b, out_cmem);
    // new_mem = x; aux = 0
    tail_kernel<<<1024, 256>>>(x, out);
}

// round 10
// speedup vs baseline: 1.8750x; 1.1620x over previous
#include <cuda_runtime.h>
#include <cuda_bf16.h>
#include <math.h>
#include <stdint.h>

// Problem constants
#define B_ 4
#define T_ 1024
#define E_ 1024
#define H_ 8
#define DH_ 128
#define KV_ 2304
#define CML_ 256
#define MEML_ 1024
#define TOTMEM_ 1280
#define SCALE_ 0.08838834764831845f

// Scratch (device globals — allocation-free rule)
__device__ float g_q[B_ * T_ * E_];      // pre-scaled, tf32-rounded
__device__ float g_k[B_ * KV_ * E_];     // tf32-rounded
__device__ float g_v[B_ * KV_ * E_];     // tf32-rounded
__device__ float g_attn[B_ * T_ * E_];   // tf32-rounded (attn epilogue)
__device__ float g_pe[H_ * KV_ * DH_];   // tf32-rounded pos_emb
__device__ float g_cwt[1024 * 4096];     // conv_w permuted to (o, r*1024+d)
// pre-rounded GEMM inputs
__device__ float g_xr[B_ * T_ * E_];
__device__ float g_memr[B_ * MEML_ * E_];
__device__ float g_cmemr[B_ * CML_ * E_];
__device__ float g_wqr[1024 * 1024];
__device__ float g_wkvr[1024 * 2048];
__device__ float g_woutr[1024 * 1024];

#define MODE_Q 0
#define MODE_KV 1
#define MODE_OUT 3
#define MODE_CMEM 4

__device__ __forceinline__ uint32_t tf32r(float f) {
    uint32_t r;
    asm("cvt.rna.tf32.f32 %0, %1;" : "=r"(r) : "f"(f));
    return r;
}
__device__ __forceinline__ float tf32f(float f) {
    return __uint_as_float(tf32r(f));
}

#define MMA_TF32(c, a0, a1, a2, a3, b0, b1) \
    asm volatile( \
        "mma.sync.aligned.m16n8k8.row.col.f32.tf32.tf32.f32 " \
        "{%0,%1,%2,%3}, {%4,%5,%6,%7}, {%8,%9}, {%0,%1,%2,%3};" \
        : "+f"((c)[0]), "+f"((c)[1]), "+f"((c)[2]), "+f"((c)[3]) \
        : "r"(a0), "r"(a1), "r"(a2), "r"(a3), "r"(b0), "r"(b1))

__device__ __forceinline__ uint32_t smem_u32(const void* p) {
    uint32_t a;
    asm("{ .reg .u64 t; cvta.to.shared.u64 t, %1; cvt.u32.u64 %0, t; }" : "=r"(a) : "l"(p));
    return a;
}
__device__ __forceinline__ void cpa16(uint32_t dst, const float* src) {
    asm volatile("cp.async.cg.shared.global [%0], [%1], 16;" :: "r"(dst), "l"(src));
}
#define CP_COMMIT() asm volatile("cp.async.commit_group;" ::: "memory")
#define CP_WAIT(n)  asm volatile("cp.async.wait_group %0;" :: "n"(n) : "memory")

// ---------------------------------------------------------------------------
// Pipelined tf32 GEMM (inputs pre-rounded): 128x128x32 tile, 3-stage cp.async,
// conflict-free fragment layouts As[m][36], Bs[k][136]. K = 1024 fixed.
// ---------------------------------------------------------------------------
#define AW 36
#define BW 136
#define ASTG (128 * AW)          // 4608 words
#define BSTG (32 * BW)           // 4352 words
#define STG  (ASTG + BSTG)       // 8960 words
#define PIPE_SMEM (STG * 3 * 4)  // 107520 bytes

template <int MODE>
__global__ void __launch_bounds__(256, 2) pipe_gemm(
    const float* __restrict__ A0, const float* __restrict__ A1,
    const float* __restrict__ A2, const float* __restrict__ Bmat,
    const float* __restrict__ bias, float* __restrict__ Cout)
{
    constexpr int NT = 32;
    constexpr int LDBN = (MODE == MODE_KV) ? 2048 : 1024;

    extern __shared__ float sm[];
    const uint32_t sb = smem_u32(sm);

    const int tid = threadIdx.x;
    const int wid = tid >> 5, lid = tid & 31;
    const int g = lid >> 2, tg = lid & 3;
    const int m0 = blockIdx.y * 128;
    const int n0 = blockIdx.x * 128;
    const int wm = (wid & 3) * 32;
    const int wn = (wid >> 2) * 64;

    const float* Abase;
    if constexpr (MODE == MODE_KV) {
        int b = m0 / KV_;
        int j = m0 - b * KV_;
        if (j < CML_)              Abase = A2 + (size_t)(b * CML_ + j) * 1024;
        else if (j < CML_ + MEML_) Abase = A1 + (size_t)(b * MEML_ + (j - CML_)) * 1024;
        else                       Abase = A0 + (size_t)(b * T_ + (j - CML_ - MEML_)) * 1024;
    } else if constexpr (MODE == MODE_OUT) {
        Abase = g_attn + (size_t)m0 * 1024;
    } else {
        Abase = A0 + (size_t)m0 * 1024;
    }
    const float* Bbase = Bmat + n0;

    const int arow0 = tid >> 3;        // 0..31
    const int ac = (tid & 7) * 4;      // 0,4,..28
    const int brow0 = tid >> 5;        // 0..7
    const int bc = (tid & 31) * 4;     // 0..124

    auto issue = [&](int t) {
        const uint32_t sa = sb + ((t % 3) * STG) * 4;
        const float* asrc = Abase + (size_t)arow0 * 1024 + t * 32 + ac;
#pragma unroll
        for (int ia = 0; ia < 4; ia++)
            cpa16(sa + ((arow0 + ia * 32) * AW + ac) * 4, asrc + (size_t)(ia * 32) * 1024);
        const uint32_t sB = sa + ASTG * 4;
        const float* bsrc = Bbase + (size_t)(t * 32 + brow0) * LDBN + bc;
#pragma unroll
        for (int ib = 0; ib < 4; ib++)
            cpa16(sB + ((brow0 + ib * 8) * BW + bc) * 4, bsrc + (size_t)(ib * 8) * LDBN);
    };

    float c[2][8][4];
#pragma unroll
    for (int mi = 0; mi < 2; mi++)
#pragma unroll
        for (int ni = 0; ni < 8; ni++)
#pragma unroll
            for (int r = 0; r < 4; r++) c[mi][ni][r] = 0.f;

    issue(0); CP_COMMIT();
    issue(1); CP_COMMIT();

    for (int t = 0; t < NT; t++) {
        if (t < NT - 1) { CP_WAIT(1); } else { CP_WAIT(0); }
        __syncthreads();
        if (t + 2 < NT) { issue(t + 2); CP_COMMIT(); }

        const uint32_t* Asu = (const uint32_t*)(sm + (t % 3) * STG);
        const uint32_t* Bsu = Asu + ASTG;
        const int r0a = (wm + g) * AW;
        const int r0b = (wm + 16 + g) * AW;
#pragma unroll
        for (int kk = 0; kk < 4; kk++) {
            const int kb = kk * 8;
            uint32_t a[2][4];
            a[0][0] = Asu[r0a + kb + tg];
            a[0][1] = Asu[r0a + 8 * AW + kb + tg];
            a[0][2] = Asu[r0a + kb + tg + 4];
            a[0][3] = Asu[r0a + 8 * AW + kb + tg + 4];
            a[1][0] = Asu[r0b + kb + tg];
            a[1][1] = Asu[r0b + 8 * AW + kb + tg];
            a[1][2] = Asu[r0b + kb + tg + 4];
            a[1][3] = Asu[r0b + 8 * AW + kb + tg + 4];
#pragma unroll
            for (int ni = 0; ni < 8; ni++) {
                uint32_t b0 = Bsu[(kb + tg) * BW + wn + 8 * ni + g];
                uint32_t b1 = Bsu[(kb + tg + 4) * BW + wn + 8 * ni + g];
#pragma unroll
                for (int mi = 0; mi < 2; mi++)
                    MMA_TF32(c[mi][ni], a[mi][0], a[mi][1], a[mi][2], a[mi][3], b0, b1);
            }
        }
        // no trailing sync: next iteration's top sync protects buffer reuse
    }

#pragma unroll
    for (int mi = 0; mi < 2; mi++) {
        const int row = m0 + wm + 16 * mi + g;
#pragma unroll
        for (int ni = 0; ni < 8; ni++) {
            const int col = n0 + wn + 8 * ni + 2 * tg;
            float2 lo = make_float2(c[mi][ni][0], c[mi][ni][1]);
            float2 hi = make_float2(c[mi][ni][2], c[mi][ni][3]);
            if constexpr (MODE == MODE_Q) {
                *(float2*)(g_q + (size_t)row * 1024 + col) =
                    make_float2(tf32f(lo.x * SCALE_), tf32f(lo.y * SCALE_));
                *(float2*)(g_q + (size_t)(row + 8) * 1024 + col) =
                    make_float2(tf32f(hi.x * SCALE_), tf32f(hi.y * SCALE_));
            } else if constexpr (MODE == MODE_KV) {
                float* base = (n0 < 1024) ? g_k : g_v;
                int cc = (n0 < 1024) ? col : col - 1024;
                *(float2*)(base + (size_t)row * 1024 + cc) =
                    make_float2(tf32f(lo.x), tf32f(lo.y));
                *(float2*)(base + (size_t)(row + 8) * 1024 + cc) =
                    make_float2(tf32f(hi.x), tf32f(hi.y));
            } else { // OUT
                float2 bb = *(const float2*)(bias + col);
                *(float2*)(Cout + (size_t)row * 1024 + col) =
                    make_float2(lo.x + bb.x, lo.y + bb.y);
                *(float2*)(Cout + (size_t)(row + 8) * 1024 + col) =
                    make_float2(hi.x + bb.x, hi.y + bb.y);
            }
        }
    }
}

// ---------------------------------------------------------------------------
// Legacy GEMM (loader-rounded) — used only for CMEM (K=4096, B transposed)
// ---------------------------------------------------------------------------
__global__ void __launch_bounds__(256) cmem_gemm(
    const float* __restrict__ A1, const float* __restrict__ Bmat,
    const float* __restrict__ bias, float* __restrict__ Cout)
{
    constexpr int K = 4096;
    constexpr int NT = K / 32;

    __shared__ uint32_t As[32][132];
    __shared__ uint32_t Bs[32][132];

    const int tid = threadIdx.x;
    const int wid = tid >> 5;
    const int lid = tid & 31;
    const int g   = lid >> 2;
    const int tg  = lid & 3;
    const int m0 = blockIdx.y * 128;
    const int n0 = blockIdx.x * 128;
    const int wm = (wid & 3) * 32;
    const int wn = (wid >> 2) * 64;

    const float* Abase = A1 + (size_t)m0 * 4096;
    const float* Bbase = Bmat + (size_t)n0 * 4096;

    const int arow = tid >> 1;
    const int akh  = (tid & 1) * 16;
    const float* aPtr = Abase + (size_t)arow * 4096 + akh;

    float4 av[4], bv[4];
    auto loadA = [&](int t) {
        const float* p = aPtr + t * 32;
#pragma unroll
        for (int j = 0; j < 4; j++) av[j] = *(const float4*)(p + 4 * j);
    };
    auto loadB = [&](int t) {
        const float* p = Bbase + (size_t)(tid >> 1) * 4096 + (tid & 1) * 16 + t * 32;
#pragma unroll
        for (int j = 0; j < 4; j++) bv[j] = *(const float4*)(p + 4 * j);
    };
    auto stsA = [&]() {
#pragma unroll
        for (int j = 0; j < 4; j++) {
            As[akh + 4 * j + 0][arow] = tf32r(av[j].x);
            As[akh + 4 * j + 1][arow] = tf32r(av[j].y);
            As[akh + 4 * j + 2][arow] = tf32r(av[j].z);
            As[akh + 4 * j + 3][arow] = tf32r(av[j].w);
        }
    };
    auto stsB = [&]() {
        const int nrow = tid >> 1;
        const int kh = (tid & 1) * 16;
#pragma unroll
        for (int j = 0; j < 4; j++) {
            Bs[kh + 4 * j + 0][nrow] = tf32r(bv[j].x);
            Bs[kh + 4 * j + 1][nrow] = tf32r(bv[j].y);
            Bs[kh + 4 * j + 2][nrow] = tf32r(bv[j].z);
            Bs[kh + 4 * j + 3][nrow] = tf32r(bv[j].w);
        }
    };

    float c[2][8][4];
#pragma unroll
    for (int mi = 0; mi < 2; mi++)
#pragma unroll
        for (int ni = 0; ni < 8; ni++)
#pragma unroll
            for (int r = 0; r < 4; r++) c[mi][ni][r] = 0.f;

    loadA(0); loadB(0);
    for (int t = 0; t < NT; t++) {
        stsA(); stsB();
        __syncthreads();
        if (t + 1 < NT) { loadA(t + 1); loadB(t + 1); }

#pragma unroll
        for (int kk = 0; kk < 4; kk++) {
            const int kb = kk * 8;
            uint32_t a[2][4];
#pragma unroll
            for (int mi = 0; mi < 2; mi++) {
                a[mi][0] = As[kb + tg][wm + 16 * mi + g];
                a[mi][1] = As[kb + tg][wm + 16 * mi + g + 8];
                a[mi][2] = As[kb + tg + 4][wm + 16 * mi + g];
                a[mi][3] = As[kb + tg + 4][wm + 16 * mi + g + 8];
            }
#pragma unroll
            for (int ni = 0; ni < 8; ni++) {
                uint32_t b0 = Bs[kb + tg][wn + 8 * ni + g];
                uint32_t b1 = Bs[kb + tg + 4][wn + 8 * ni + g];
#pragma unroll
                for (int mi = 0; mi < 2; mi++)
                    MMA_TF32(c[mi][ni], a[mi][0], a[mi][1], a[mi][2], a[mi][3], b0, b1);
            }
        }
        __syncthreads();
    }

#pragma unroll
    for (int mi = 0; mi < 2; mi++) {
        const int row = m0 + wm + 16 * mi + g;
#pragma unroll
        for (int ni = 0; ni < 8; ni++) {
            const int col = n0 + wn + 8 * ni + 2 * tg;
            float2 bb = *(const float2*)(bias + col);
            *(float2*)(Cout + (size_t)row * 1024 + col) =
                make_float2(c[mi][ni][0] + bb.x, c[mi][ni][1] + bb.y);
            *(float2*)(Cout + (size_t)(row + 8) * 1024 + col) =
                make_float2(c[mi][ni][2] + bb.x, c[mi][ni][3] + bb.y);
        }
    }
}

// conv_w (o, d, r) -> (o, r*1024 + d)
__global__ void convw_kernel(const float* __restrict__ in, float* __restrict__ out)
{
    int i = blockIdx.x * 256 + threadIdx.x;
    int o = i >> 12, rem = i & 4095, d = rem >> 2, r = rem & 3;
    out[(size_t)o * 4096 + r * 1024 + d] = in[i];
}

// tf32-round copy (float4)
__global__ void round4_kernel(const float4* __restrict__ in, float4* __restrict__ out, int n4)
{
    int i = blockIdx.x * 256 + threadIdx.x;
    if (i < n4) {
        float4 v = in[i];
        out[i] = make_float4(tf32f(v.x), tf32f(v.y), tf32f(v.z), tf32f(v.w));
    }
}

// ---------------------------------------------------------------------------
// Tensor-core flash attention v3 (unchanged math; epilogue now tf32-rounds)
// ---------------------------------------------------------------------------
#define KS_OFF   0
#define PE_OFF   16896
#define VS_OFF   33792
#define SS_OFF   42496
#define S2_OFF   46848
#define CORR_OFF 55552
#define INVL_OFF 55616
#define ATT_SMEM (55680 * 4)

__global__ void __launch_bounds__(256, 1) attn_kernel()
{
    extern __shared__ float smf[];
    const uint32_t sb = smem_u32(smf);
    uint32_t* W = (uint32_t*)smf;
    float*    Ss = smf + SS_OFF;
    uint32_t* Ssu = (uint32_t*)Ss;
    float*    corr_s = smf + CORR_OFF;
    float*    invl_s = smf + INVL_OFF;

    const int tid = threadIdx.x;
    const int wid = tid >> 5, lid = tid & 31;
    const int g = lid >> 2, tg = lid & 3;
    const int wm = (wid & 3) * 16;
    const int half = wid >> 2;
    const int tx = tid & 15, ty = tid >> 4;
    const int qx = 15 - (int)blockIdx.x;
    const int q0 = qx * 64;
    const int bh = blockIdx.y;
    const int b = bh >> 3, h = bh & 7;
    const int n_tiles = qx + 21;
    const int P0 = 15 - qx;

    const int ldr = tid >> 2;
    const int ldc0 = tid & 3;
    const float* peh = g_pe + (size_t)h * KV_ * 128;

    auto issueK = [&](int t) {
        const int m0 = (t < n_tiles) ? t * 64 : 0;
        const float* src = g_k + ((size_t)(b * KV_ + m0 + ldr)) * 1024 + h * 128;
        const uint32_t dst = sb + (KS_OFF + (t & 1) * 8448 + ldr * 132) * 4;
#pragma unroll
        for (int i = 0; i < 8; i++) { int c = ldc0 + 4 * i; cpa16(dst + c * 16, src + c * 4); }
    };
    auto issueV = [&](int t) {
        const int m0 = (t < n_tiles) ? t * 64 : 0;
        const float* src = g_v + ((size_t)(b * KV_ + m0 + ldr)) * 1024 + h * 128;
        const uint32_t dst = sb + (VS_OFF + ldr * 136) * 4;
#pragma unroll
        for (int i = 0; i < 8; i++) { int c = ldc0 + 4 * i; cpa16(dst + c * 16, src + c * 4); }
    };
    auto issuePE = [&](int page) {
        int r = page * 64 + ldr;
        if ((unsigned)r >= (unsigned)KV_) r = 0;
        const float* src = peh + (size_t)r * 128;
        const uint32_t dst = sb + (PE_OFF + (page & 1) * 8448 + ldr * 132) * 4;
#pragma unroll
        for (int i = 0; i < 8; i++) { int c = ldc0 + 4 * i; cpa16(dst + c * 16, src + c * 4); }
    };

    issueK(0); issuePE(P0); issuePE(P0 + 1);
    CP_COMMIT();
    issueV(0);
    CP_COMMIT();

    uint32_t qf[16][4];
    {
        const float* q0p = g_q + ((size_t)(b * T_ + q0 + wm + g)) * 1024 + h * 128;
        const float* q8p = q0p + 8 * 1024;
#pragma unroll
        for (int kb8 = 0; kb8 < 16; kb8++) {
            const int c = kb8 * 8 + tg;
            qf[kb8][0] = __float_as_uint(q0p[c]);
            qf[kb8][1] = __float_as_uint(q8p[c]);
            qf[kb8][2] = __float_as_uint(q0p[c + 4]);
            qf[kb8][3] = __float_as_uint(q8p[c + 4]);
        }
    }

    float o[8][4];
#pragma unroll
    for (int d = 0; d < 8; d++)
#pragma unroll
        for (int r = 0; r < 4; r++) o[d][r] = 0.f;
    float m_run[4], l_run[4];
#pragma unroll
    for (int i = 0; i < 4; i++) { m_run[i] = -INFINITY; l_run[i] = 0.f; }

    auto s2page = [&](int page) {
        const uint32_t* PEb = W + PE_OFF + (page & 1) * 8448;
        float* outp = smf + S2_OFF + (page & 1) * 4352;
        float c2[4][4];
#pragma unroll
        for (int vf = 0; vf < 4; vf++)
#pragma unroll
            for (int r = 0; r < 4; r++) c2[vf][r] = 0.f;
#pragma unroll
        for (int kb8 = 0; kb8 < 16; kb8++) {
            const int kb = kb8 * 8;
#pragma unroll
            for (int vf = 0; vf < 4; vf++) {
                const int n = half * 32 + vf * 8 + g;
                uint32_t b0 = PEb[n * 132 + kb + tg];
                uint32_t b1 = PEb[n * 132 + kb + tg + 4];
                MMA_TF32(c2[vf], qf[kb8][0], qf[kb8][1], qf[kb8][2], qf[kb8][3], b0, b1);
            }
        }
#pragma unroll
        for (int vf = 0; vf < 4; vf++) {
            const int col = half * 32 + vf * 8 + 2 * tg;
            *(float2*)(outp + (wm + g) * 68 + col) = make_float2(c2[vf][0], c2[vf][1]);
            *(float2*)(outp + (wm + g + 8) * 68 + col) = make_float2(c2[vf][2], c2[vf][3]);
        }
    };

    CP_WAIT(1);
    __syncthreads();
    s2page(P0);

    for (int t = 0; t < n_tiles; t++) {
        const int m0 = t * 64;
        const int Pb = t - qx + 15;

        CP_WAIT(1);
        __syncthreads();

        // ---- S1 = Q @ K^T ----
        {
            const uint32_t* Kw = W + KS_OFF + (t & 1) * 8448;
            float c1[4][4];
#pragma unroll
            for (int nf = 0; nf < 4; nf++)
#pragma unroll
                for (int r = 0; r < 4; r++) c1[nf][r] = 0.f;
#pragma unroll
            for (int kb8 = 0; kb8 < 16; kb8++) {
                const int kb = kb8 * 8;
#pragma unroll
                for (int nf = 0; nf < 4; nf++) {
                    const int n = half * 32 + nf * 8 + g;
                    uint32_t b0 = Kw[n * 132 + kb + tg];
                    uint32_t b1 = Kw[n * 132 + kb + tg + 4];
                    MMA_TF32(c1[nf], qf[kb8][0], qf[kb8][1], qf[kb8][2], qf[kb8][3], b0, b1);
                }
            }
#pragma unroll
            for (int nf = 0; nf < 4; nf++) {
                const int col = half * 32 + nf * 8 + 2 * tg;
                *(float2*)(Ss + (wm + g) * 68 + col) = make_float2(c1[nf][0], c1[nf][1]);
                *(float2*)(Ss + (wm + g + 8) * 68 + col) = make_float2(c1[nf][2], c1[nf][3]);
            }
        }

        s2page(Pb + 1);
        __syncthreads();

        issueK(t + 1); issuePE(Pb + 2);
        CP_COMMIT();

        // ---- softmax ----
        {
            const float* S2a = smf + S2_OFF + (Pb & 1) * 4352;
            const float* S2b = smf + S2_OFF + ((Pb + 1) & 1) * 4352;
#pragma unroll
            for (int ii = 0; ii < 4; ii++) {
                const int i = ty + 16 * ii;
                const int qg = q0 + i;
                float s[4];
#pragma unroll
                for (int jj = 0; jj < 4; jj++) {
                    const int j = tx + 16 * jj;
                    const int u = 63 + j - i;
                    float pv = (u < 64) ? S2a[i * 68 + u] : S2b[i * 68 + u - 64];
                    s[jj] = Ss[i * 68 + j] + pv;
                    if (m0 + j > qg + TOTMEM_) s[jj] = -INFINITY;
                }
                float mx = fmaxf(fmaxf(s[0], s[1]), fmaxf(s[2], s[3]));
                mx = fmaxf(mx, __shfl_xor_sync(0xffffffffu, mx, 1, 16));
                mx = fmaxf(mx, __shfl_xor_sync(0xffffffffu, mx, 2, 16));
                mx = fmaxf(mx, __shfl_xor_sync(0xffffffffu, mx, 4, 16));
                mx = fmaxf(mx, __shfl_xor_sync(0xffffffffu, mx, 8, 16));
                float m_new = fmaxf(m_run[ii], mx);
                float corrv = __expf(m_run[ii] - m_new);
                float p0 = __expf(s[0] - m_new);
                float p1 = __expf(s[1] - m_new);
                float p2 = __expf(s[2] - m_new);
                float p3 = __expf(s[3] - m_new);
                float sum = p0 + p1 + p2 + p3;
                sum += __shfl_xor_sync(0xffffffffu, sum, 1, 16);
                sum += __shfl_xor_sync(0xffffffffu, sum, 2, 16);
                sum += __shfl_xor_sync(0xffffffffu, sum, 4, 16);
                sum += __shfl_xor_sync(0xffffffffu, sum, 8, 16);
                l_run[ii] = l_run[ii] * corrv + sum;
                m_run[ii] = m_new;
                Ssu[i * 68 + tx]      = tf32r(p0);
                Ssu[i * 68 + tx + 16] = tf32r(p1);
                Ssu[i * 68 + tx + 32] = tf32r(p2);
                Ssu[i * 68 + tx + 48] = tf32r(p3);
                if (tx == 0) corr_s[i] = corrv;
            }
        }

        CP_WAIT(1);
        __syncthreads();

        // ---- PV ----
        {
            const uint32_t* Vw = W + VS_OFF;
            const float cr0 = corr_s[wm + g];
            const float cr8 = corr_s[wm + g + 8];
#pragma unroll
            for (int df = 0; df < 8; df++) {
                o[df][0] *= cr0; o[df][1] *= cr0;
                o[df][2] *= cr8; o[df][3] *= cr8;
            }
#pragma unroll
            for (int kb8 = 0; kb8 < 8; kb8++) {
                const int kb = kb8 * 8;
                uint32_t a0 = Ssu[(wm + g) * 68 + kb + tg];
                uint32_t a1 = Ssu[(wm + g + 8) * 68 + kb + tg];
                uint32_t a2 = Ssu[(wm + g) * 68 + kb + tg + 4];
                uint32_t a3 = Ssu[(wm + g + 8) * 68 + kb + tg + 4];
#pragma unroll
                for (int df = 0; df < 8; df++) {
                    uint32_t b0 = Vw[(kb + tg) * 136 + half * 64 + df * 8 + g];
                    uint32_t b1 = Vw[(kb + tg + 4) * 136 + half * 64 + df * 8 + g];
                    MMA_TF32(o[df], a0, a1, a2, a3, b0, b1);
                }
            }
        }
        __syncthreads();

        issueV(t + 1);
        CP_COMMIT();
    }

    CP_WAIT(0);
    if (tx == 0) {
#pragma unroll
        for (int ii = 0; ii < 4; ii++)
            invl_s[ty + 16 * ii] = 1.f / l_run[ii];
    }
    __syncthreads();
    const float il0 = invl_s[wm + g];
    const float il8 = invl_s[wm + g + 8];
    const int row0 = q0 + wm + g;
#pragma unroll
    for (int df = 0; df < 8; df++) {
        const int col = h * 128 + half * 64 + df * 8 + 2 * tg;
        *(float2*)(g_attn + ((size_t)(b * T_ + row0)) * 1024 + col) =
            make_float2(tf32f(o[df][0] * il0), tf32f(o[df][1] * il0));
        *(float2*)(g_attn + ((size_t)(b * T_ + row0 + 8)) * 1024 + col) =
            make_float2(tf32f(o[df][2] * il8), tf32f(o[df][3] * il8));
    }
}

// ---------------------------------------------------------------------------
// Tail: new_mem = x (copy), aux_loss = 0
// ---------------------------------------------------------------------------
__global__ void tail_kernel(const float* __restrict__ x, float* __restrict__ out)
{
    const size_t n4 = (size_t)B_ * T_ * E_ / 4;
    float4* dst = (float4*)(out + (size_t)B_ * T_ * E_);
    const float4* src = (const float4*)x;
    size_t i = (size_t)blockIdx.x * blockDim.x + threadIdx.x;
    for (size_t k = i; k < n4; k += (size_t)gridDim.x * blockDim.x) dst[k] = src[k];
    if (i == 0)
        out[(size_t)B_ * T_ * E_ * 2 + (size_t)B_ * CML_ * E_] = 0.f;
}

// ---------------------------------------------------------------------------
extern "C" void kernel_launch(void* const* d_in, const int* in_sizes, int n_in,
                              void* d_out, int out_size)
{
    (void)in_sizes; (void)n_in;
    const float* x      = (const float*)d_in[0];
    const float* mem    = (const float*)d_in[1];
    const float* cmem   = (const float*)d_in[2];
    const float* pe     = (const float*)d_in[3];
    const float* Wq     = (const float*)d_in[5];
    const float* Wkv    = (const float*)d_in[6];
    const float* Wout   = (const float*)d_in[7];
    const float* b_out  = (const float*)d_in[8];
    const float* conv_w = (const float*)d_in[9];
    const float* conv_b = (const float*)d_in[10];

    float* out = (float*)d_out;
    float* out_logits = out;
    float* out_cmem   = out + (size_t)2 * B_ * T_ * E_;

    float *cwt, *gpe, *xr, *memr, *cmemr, *wqr, *wkvr, *woutr;
    cudaGetSymbolAddress((void**)&cwt, g_cwt);
    cudaGetSymbolAddress((void**)&gpe, g_pe);
    cudaGetSymbolAddress((void**)&xr, g_xr);
    cudaGetSymbolAddress((void**)&memr, g_memr);
    cudaGetSymbolAddress((void**)&cmemr, g_cmemr);
    cudaGetSymbolAddress((void**)&wqr, g_wqr);
    cudaGetSymbolAddress((void**)&wkvr, g_wkvr);
    cudaGetSymbolAddress((void**)&woutr, g_woutr);

    cudaFuncSetAttribute(attn_kernel, cudaFuncAttributeMaxDynamicSharedMemorySize, ATT_SMEM);
    cudaFuncSetAttribute(pipe_gemm<MODE_Q>,   cudaFuncAttributeMaxDynamicSharedMemorySize, PIPE_SMEM);
    cudaFuncSetAttribute(pipe_gemm<MODE_KV>,  cudaFuncAttributeMaxDynamicSharedMemorySize, PIPE_SMEM);
    cudaFuncSetAttribute(pipe_gemm<MODE_OUT>, cudaFuncAttributeMaxDynamicSharedMemorySize, PIPE_SMEM);

    // pre-processing
    convw_kernel<<<16384, 256>>>(conv_w, cwt);
    pe_round_dispatch:
    {
        // pos_emb rounded copy (reuse round4)
        round4_kernel<<<(H_ * KV_ * DH_ / 4 + 255) / 256, 256>>>((const float4*)pe, (float4*)gpe, H_ * KV_ * DH_ / 4);
    }
    round4_kernel<<<(B_ * T_ * E_ / 4 + 255) / 256, 256>>>((const float4*)x, (float4*)xr, B_ * T_ * E_ / 4);
    round4_kernel<<<(B_ * MEML_ * E_ / 4 + 255) / 256, 256>>>((const float4*)mem, (float4*)memr, B_ * MEML_ * E_ / 4);
    round4_kernel<<<(B_ * CML_ * E_ / 4 + 255) / 256, 256>>>((const float4*)cmem, (float4*)cmemr, B_ * CML_ * E_ / 4);
    round4_kernel<<<(1024 * 1024 / 4 + 255) / 256, 256>>>((const float4*)Wq, (float4*)wqr, 1024 * 1024 / 4);
    round4_kernel<<<(1024 * 2048 / 4 + 255) / 256, 256>>>((const float4*)Wkv, (float4*)wkvr, 1024 * 2048 / 4);
    round4_kernel<<<(1024 * 1024 / 4 + 255) / 256, 256>>>((const float4*)Wout, (float4*)woutr, 1024 * 1024 / 4);

    // q = x @ Wq  (epilogue: *SCALE, tf32 round)
    pipe_gemm<MODE_Q><<<dim3(8, 32), 256, PIPE_SMEM>>>(xr, nullptr, nullptr, wqr, nullptr, nullptr);
    // kv = [cmem;mem;x] @ Wkv  (epilogue: tf32 round)
    pipe_gemm<MODE_KV><<<dim3(16, 72), 256, PIPE_SMEM>>>(xr, memr, cmemr, wkvr, nullptr, nullptr);
    // attention
    attn_kernel<<<dim3(16, 32), 256, ATT_SMEM>>>();
    // logits = attn_out @ Wout + b_out
    pipe_gemm<MODE_OUT><<<dim3(8, 32), 256, PIPE_SMEM>>>(nullptr, nullptr, nullptr, woutr, b_out, out_logits);
    // new_cmem = conv(mem)  (legacy kernel, loader-rounded)
    cmem_gemm<<<dim3(8, 8), 256>>>(mem, cwt, conv_b, out_cmem);
    // new_mem = x; aux = 0
    tail_kernel<<<1024, 256>>>(x, out);
}

// round 13
// speedup vs baseline: 2.1750x; 1.1600x over previous
#include <cuda_runtime.h>
#include <cuda_bf16.h>
#include <math.h>
#include <stdint.h>

// Problem constants
#define B_ 4
#define T_ 1024
#define E_ 1024
#define H_ 8
#define DH_ 128
#define KV_ 2304
#define CML_ 256
#define MEML_ 1024
#define TOTMEM_ 1280
#define SCALE_ 0.08838834764831845f

// Scratch (device globals — allocation-free rule)
__device__ float g_q[B_ * T_ * E_];      // pre-scaled, tf32-rounded
__device__ float g_k[B_ * KV_ * E_];     // tf32-rounded
__device__ float g_v[B_ * KV_ * E_];     // tf32-rounded
__device__ float g_attn[B_ * T_ * E_];   // tf32-rounded (attn epilogue)
__device__ float g_pe[H_ * KV_ * DH_];   // tf32-rounded pos_emb
__device__ float g_cwt[1024 * 4096];     // conv_w permuted to (o, r*1024+d)
// pre-rounded GEMM inputs
__device__ float g_xr[B_ * T_ * E_];
__device__ float g_memr[B_ * MEML_ * E_];
__device__ float g_cmemr[B_ * CML_ * E_];
__device__ float g_wqr[1024 * 1024];
__device__ float g_wkvr[1024 * 2048];
__device__ float g_woutr[1024 * 1024];

__device__ __forceinline__ uint32_t tf32r(float f) {
    uint32_t r;
    asm("cvt.rna.tf32.f32 %0, %1;" : "=r"(r) : "f"(f));
    return r;
}
__device__ __forceinline__ float tf32f(float f) {
    return __uint_as_float(tf32r(f));
}

#define MMA_TF32(c, a0, a1, a2, a3, b0, b1) \
    asm volatile( \
        "mma.sync.aligned.m16n8k8.row.col.f32.tf32.tf32.f32 " \
        "{%0,%1,%2,%3}, {%4,%5,%6,%7}, {%8,%9}, {%0,%1,%2,%3};" \
        : "+f"((c)[0]), "+f"((c)[1]), "+f"((c)[2]), "+f"((c)[3]) \
        : "r"(a0), "r"(a1), "r"(a2), "r"(a3), "r"(b0), "r"(b1))

__device__ __forceinline__ uint32_t smem_u32(const void* p) {
    uint32_t a;
    asm("{ .reg .u64 t; cvta.to.shared.u64 t, %1; cvt.u32.u64 %0, t; }" : "=r"(a) : "l"(p));
    return a;
}
__device__ __forceinline__ void cpa16(uint32_t dst, const float* src) {
    asm volatile("cp.async.cg.shared.global [%0], [%1], 16;" :: "r"(dst), "l"(src));
}
#define CP_COMMIT() asm volatile("cp.async.commit_group;" ::: "memory")
#define CP_WAIT(n)  asm volatile("cp.async.wait_group %0;" :: "n"(n) : "memory")

// ---------------------------------------------------------------------------
// Shared pipelined-GEMM mainloop (inputs pre-rounded, K=1024, 3-stage)
// As[m][36] / Bs[k][136] conflict-free layouts.
// ---------------------------------------------------------------------------
#define AW 36
#define BW 136
#define ASTG (128 * AW)          // 4608 words
#define BSTG (32 * BW)           // 4352 words
#define STG  (ASTG + BSTG)       // 8960 words
#define PIPE_SMEM (STG * 3 * 4)  // 107520 bytes

__device__ __forceinline__ void pipe_loop(
    float* sm, uint32_t sb, const float* Abase, const float* Bbase, int ldbn,
    int tid, int wm, int wn, int g, int tg, float c[2][8][4])
{
    const int arow0 = tid >> 3;
    const int ac = (tid & 7) * 4;
    const int brow0 = tid >> 5;
    const int bc = (tid & 31) * 4;

    auto issue = [&](int t) {
        const uint32_t sa = sb + ((t % 3) * STG) * 4;
        const float* asrc = Abase + (size_t)arow0 * 1024 + t * 32 + ac;
#pragma unroll
        for (int ia = 0; ia < 4; ia++)
            cpa16(sa + ((arow0 + ia * 32) * AW + ac) * 4, asrc + (size_t)(ia * 32) * 1024);
        const uint32_t sB = sa + ASTG * 4;
        const float* bsrc = Bbase + (size_t)(t * 32 + brow0) * ldbn + bc;
#pragma unroll
        for (int ib = 0; ib < 4; ib++)
            cpa16(sB + ((brow0 + ib * 8) * BW + bc) * 4, bsrc + (size_t)(ib * 8) * ldbn);
    };

    issue(0); CP_COMMIT();
    issue(1); CP_COMMIT();

    for (int t = 0; t < 32; t++) {
        if (t < 31) { CP_WAIT(1); } else { CP_WAIT(0); }
        __syncthreads();
        if (t + 2 < 32) { issue(t + 2); CP_COMMIT(); }

        const uint32_t* Asu = (const uint32_t*)(sm + (t % 3) * STG);
        const uint32_t* Bsu = Asu + ASTG;
        const int r0a = (wm + g) * AW;
        const int r0b = (wm + 16 + g) * AW;
#pragma unroll
        for (int kk = 0; kk < 4; kk++) {
            const int kb = kk * 8;
            uint32_t a[2][4];
            a[0][0] = Asu[r0a + kb + tg];
            a[0][1] = Asu[r0a + 8 * AW + kb + tg];
            a[0][2] = Asu[r0a + kb + tg + 4];
            a[0][3] = Asu[r0a + 8 * AW + kb + tg + 4];
            a[1][0] = Asu[r0b + kb + tg];
            a[1][1] = Asu[r0b + 8 * AW + kb + tg];
            a[1][2] = Asu[r0b + kb + tg + 4];
            a[1][3] = Asu[r0b + 8 * AW + kb + tg + 4];
#pragma unroll
            for (int ni = 0; ni < 8; ni++) {
                uint32_t b0 = Bsu[(kb + tg) * BW + wn + 8 * ni + g];
                uint32_t b1 = Bsu[(kb + tg + 4) * BW + wn + 8 * ni + g];
#pragma unroll
                for (int mi = 0; mi < 2; mi++)
                    MMA_TF32(c[mi][ni], a[mi][0], a[mi][1], a[mi][2], a[mi][3], b0, b1);
            }
        }
    }
}

// ---------------------------------------------------------------------------
// Fused QKV + CMEM kernel. 1D grid, 1472 CTAs:
//   [0,64)      CMEM tiles (K=4096 legacy loader-rounded path; longest first)
//   [64,1216)   KV tiles   (16 n-tiles x 72 m-tiles)
//   [1216,1472) Q tiles    (8 n-tiles x 32 m-tiles)
// ---------------------------------------------------------------------------
__global__ void __launch_bounds__(256, 2) qkv_cmem_kernel(
    const float* __restrict__ mem_raw, const float* __restrict__ conv_b,
    float* __restrict__ out_cmem)
{
    extern __shared__ float sm[];
    const uint32_t sb = smem_u32(sm);
    const int tid = threadIdx.x;
    const int wid = tid >> 5, lid = tid & 31;
    const int g = lid >> 2, tg = lid & 3;
    const int wm = (wid & 3) * 32;
    const int wn = (wid >> 2) * 64;
    const int idx = blockIdx.x;

    if (idx < 64) {
        // ================= CMEM (legacy loader-rounded, K=4096) ============
        const int n0 = (idx & 7) * 128;
        const int m0 = (idx >> 3) * 128;
        uint32_t* As = (uint32_t*)sm;          // [32][132]
        uint32_t* Bs = As + 32 * 132;          // [32][132]

        const float* Abase = mem_raw + (size_t)m0 * 4096;
        const float* Bbase = g_cwt + (size_t)n0 * 4096;

        const int arow = tid >> 1;
        const int akh  = (tid & 1) * 16;
        const float* aPtr = Abase + (size_t)arow * 4096 + akh;
        const float* bPtr = Bbase + (size_t)arow * 4096 + akh;

        float4 av[4], bv[4];
        auto loadT = [&](int t) {
#pragma unroll
            for (int j = 0; j < 4; j++) av[j] = *(const float4*)(aPtr + t * 32 + 4 * j);
#pragma unroll
            for (int j = 0; j < 4; j++) bv[j] = *(const float4*)(bPtr + t * 32 + 4 * j);
        };
        auto stsT = [&]() {
#pragma unroll
            for (int j = 0; j < 4; j++) {
                As[(akh + 4 * j + 0) * 132 + arow] = tf32r(av[j].x);
                As[(akh + 4 * j + 1) * 132 + arow] = tf32r(av[j].y);
                As[(akh + 4 * j + 2) * 132 + arow] = tf32r(av[j].z);
                As[(akh + 4 * j + 3) * 132 + arow] = tf32r(av[j].w);
                Bs[(akh + 4 * j + 0) * 132 + arow] = tf32r(bv[j].x);
                Bs[(akh + 4 * j + 1) * 132 + arow] = tf32r(bv[j].y);
                Bs[(akh + 4 * j + 2) * 132 + arow] = tf32r(bv[j].z);
                Bs[(akh + 4 * j + 3) * 132 + arow] = tf32r(bv[j].w);
            }
        };

        float c[2][8][4];
#pragma unroll
        for (int mi = 0; mi < 2; mi++)
#pragma unroll
            for (int ni = 0; ni < 8; ni++)
#pragma unroll
                for (int r = 0; r < 4; r++) c[mi][ni][r] = 0.f;

        loadT(0);
        for (int t = 0; t < 128; t++) {
            stsT();
            __syncthreads();
            if (t + 1 < 128) loadT(t + 1);
#pragma unroll
            for (int kk = 0; kk < 4; kk++) {
                const int kb = kk * 8;
                uint32_t a[2][4];
#pragma unroll
                for (int mi = 0; mi < 2; mi++) {
                    a[mi][0] = As[(kb + tg) * 132 + wm + 16 * mi + g];
                    a[mi][1] = As[(kb + tg) * 132 + wm + 16 * mi + g + 8];
                    a[mi][2] = As[(kb + tg + 4) * 132 + wm + 16 * mi + g];
                    a[mi][3] = As[(kb + tg + 4) * 132 + wm + 16 * mi + g + 8];
                }
#pragma unroll
                for (int ni = 0; ni < 8; ni++) {
                    uint32_t b0 = Bs[(kb + tg) * 132 + wn + 8 * ni + g];
                    uint32_t b1 = Bs[(kb + tg + 4) * 132 + wn + 8 * ni + g];
#pragma unroll
                    for (int mi = 0; mi < 2; mi++)
                        MMA_TF32(c[mi][ni], a[mi][0], a[mi][1], a[mi][2], a[mi][3], b0, b1);
                }
            }
            __syncthreads();
        }

#pragma unroll
        for (int mi = 0; mi < 2; mi++) {
            const int row = m0 + wm + 16 * mi + g;
#pragma unroll
            for (int ni = 0; ni < 8; ni++) {
                const int col = n0 + wn + 8 * ni + 2 * tg;
                float2 bb = *(const float2*)(conv_b + col);
                *(float2*)(out_cmem + (size_t)row * 1024 + col) =
                    make_float2(c[mi][ni][0] + bb.x, c[mi][ni][1] + bb.y);
                *(float2*)(out_cmem + (size_t)(row + 8) * 1024 + col) =
                    make_float2(c[mi][ni][2] + bb.x, c[mi][ni][3] + bb.y);
            }
        }
        return;
    }

    // ================= KV / Q (pipelined, pre-rounded inputs) ==============
    int mode, m0, n0, ldbn;
    const float *Abase, *Bbase;
    if (idx < 1216) {
        const int i2 = idx - 64;
        n0 = (i2 & 15) * 128;
        m0 = (i2 >> 4) * 128;
        mode = 1;
        ldbn = 2048;
        int b = m0 / KV_;
        int j = m0 - b * KV_;
        if (j < CML_)              Abase = g_cmemr + (size_t)(b * CML_ + j) * 1024;
        else if (j < CML_ + MEML_) Abase = g_memr + (size_t)(b * MEML_ + (j - CML_)) * 1024;
        else                       Abase = g_xr + (size_t)(b * T_ + (j - CML_ - MEML_)) * 1024;
        Bbase = g_wkvr + n0;
    } else {
        const int i3 = idx - 1216;
        n0 = (i3 & 7) * 128;
        m0 = (i3 >> 3) * 128;
        mode = 0;
        ldbn = 1024;
        Abase = g_xr + (size_t)m0 * 1024;
        Bbase = g_wqr + n0;
    }

    float c[2][8][4];
#pragma unroll
    for (int mi = 0; mi < 2; mi++)
#pragma unroll
        for (int ni = 0; ni < 8; ni++)
#pragma unroll
            for (int r = 0; r < 4; r++) c[mi][ni][r] = 0.f;

    pipe_loop(sm, sb, Abase, Bbase, ldbn, tid, wm, wn, g, tg, c);

#pragma unroll
    for (int mi = 0; mi < 2; mi++) {
        const int row = m0 + wm + 16 * mi + g;
#pragma unroll
        for (int ni = 0; ni < 8; ni++) {
            const int col = n0 + wn + 8 * ni + 2 * tg;
            float2 lo = make_float2(c[mi][ni][0], c[mi][ni][1]);
            float2 hi = make_float2(c[mi][ni][2], c[mi][ni][3]);
            if (mode == 0) {
                *(float2*)(g_q + (size_t)row * 1024 + col) =
                    make_float2(tf32f(lo.x * SCALE_), tf32f(lo.y * SCALE_));
                *(float2*)(g_q + (size_t)(row + 8) * 1024 + col) =
                    make_float2(tf32f(hi.x * SCALE_), tf32f(hi.y * SCALE_));
            } else {
                float* base = (n0 < 1024) ? g_k : g_v;
                int cc = (n0 < 1024) ? col : col - 1024;
                *(float2*)(base + (size_t)row * 1024 + cc) =
                    make_float2(tf32f(lo.x), tf32f(lo.y));
                *(float2*)(base + (size_t)(row + 8) * 1024 + cc) =
                    make_float2(tf32f(hi.x), tf32f(hi.y));
            }
        }
    }
}

// ---------------------------------------------------------------------------
// OUT GEMM: logits = attn @ Wout + b_out (pipelined)
// ---------------------------------------------------------------------------
__global__ void __launch_bounds__(256, 2) out_gemm(
    const float* __restrict__ bias, float* __restrict__ Cout)
{
    extern __shared__ float sm[];
    const uint32_t sb = smem_u32(sm);
    const int tid = threadIdx.x;
    const int wid = tid >> 5, lid = tid & 31;
    const int g = lid >> 2, tg = lid & 3;
    const int wm = (wid & 3) * 32;
    const int wn = (wid >> 2) * 64;
    const int m0 = blockIdx.y * 128;
    const int n0 = blockIdx.x * 128;

    const float* Abase = g_attn + (size_t)m0 * 1024;
    const float* Bbase = g_woutr + n0;

    float c[2][8][4];
#pragma unroll
    for (int mi = 0; mi < 2; mi++)
#pragma unroll
        for (int ni = 0; ni < 8; ni++)
#pragma unroll
            for (int r = 0; r < 4; r++) c[mi][ni][r] = 0.f;

    pipe_loop(sm, sb, Abase, Bbase, 1024, tid, wm, wn, g, tg, c);

#pragma unroll
    for (int mi = 0; mi < 2; mi++) {
        const int row = m0 + wm + 16 * mi + g;
#pragma unroll
        for (int ni = 0; ni < 8; ni++) {
            const int col = n0 + wn + 8 * ni + 2 * tg;
            float2 bb = *(const float2*)(bias + col);
            *(float2*)(Cout + (size_t)row * 1024 + col) =
                make_float2(c[mi][ni][0] + bb.x, c[mi][ni][1] + bb.y);
            *(float2*)(Cout + (size_t)(row + 8) * 1024 + col) =
                make_float2(c[mi][ni][2] + bb.x, c[mi][ni][3] + bb.y);
        }
    }
}

// ---------------------------------------------------------------------------
// Fused preprocessing: tf32-round copies, conv_w permute, new_mem copy, aux.
// Segment boundaries in float4 units (hardcoded).
// ---------------------------------------------------------------------------
#define SEG_PE    589824u
#define SEG_X     1638400u
#define SEG_MEM   2686976u
#define SEG_CMEM  2949120u
#define SEG_WQ    3211264u
#define SEG_WKV   3735552u
#define SEG_WOUT  3997696u
#define SEG_XCOPY 5046272u
#define SEG_TOTAL 6094848u

__global__ void pre_kernel(
    const float4* __restrict__ pe, const float4* __restrict__ x,
    const float4* __restrict__ mem, const float4* __restrict__ cmem,
    const float4* __restrict__ Wq, const float4* __restrict__ Wkv,
    const float4* __restrict__ Wout, const float4* __restrict__ conv_w,
    float* __restrict__ out)
{
    const uint32_t i = blockIdx.x * 256 + threadIdx.x;
    if (i >= SEG_TOTAL) return;

    auto r4 = [](float4 v) {
        return make_float4(tf32f(v.x), tf32f(v.y), tf32f(v.z), tf32f(v.w));
    };

    if (i < SEG_PE) {
        ((float4*)g_pe)[i] = r4(pe[i]);
    } else if (i < SEG_X) {
        uint32_t j = i - SEG_PE;
        ((float4*)g_xr)[j] = r4(x[j]);
    } else if (i < SEG_MEM) {
        uint32_t j = i - SEG_X;
        ((float4*)g_memr)[j] = r4(mem[j]);
    } else if (i < SEG_CMEM) {
        uint32_t j = i - SEG_MEM;
        ((float4*)g_cmemr)[j] = r4(cmem[j]);
    } else if (i < SEG_WQ) {
        uint32_t j = i - SEG_CMEM;
        ((float4*)g_wqr)[j] = r4(Wq[j]);
    } else if (i < SEG_WKV) {
        uint32_t j = i - SEG_WQ;
        ((float4*)g_wkvr)[j] = r4(Wkv[j]);
    } else if (i < SEG_WOUT) {
        uint32_t j = i - SEG_WKV;
        ((float4*)g_woutr)[j] = r4(Wout[j]);
    } else if (i < SEG_XCOPY) {
        uint32_t j = i - SEG_WOUT;
        ((float4*)(out + (size_t)B_ * T_ * E_))[j] = x[j];   // new_mem = x
        if (j == 0)
            out[(size_t)B_ * T_ * E_ * 2 + (size_t)B_ * CML_ * E_] = 0.f;  // aux
    } else {
        uint32_t j = i - SEG_XCOPY;          // conv_w permute (1,048,576 float4)
        uint32_t o = j >> 10, d = j & 1023;
        float4 v = conv_w[j];                // (o, d, r=0..3)
        float* dst = g_cwt + (size_t)o * 4096 + d;
        dst[0]    = v.x;
        dst[1024] = v.y;
        dst[2048] = v.z;
        dst[3072] = v.w;
    }
}

// ---------------------------------------------------------------------------
// Tensor-core flash attention v3 (unchanged from round 10)
// ---------------------------------------------------------------------------
#define KS_OFF   0
#define PE_OFF   16896
#define VS_OFF   33792
#define SS_OFF   42496
#define S2_OFF   46848
#define CORR_OFF 55552
#define INVL_OFF 55616
#define ATT_SMEM (55680 * 4)

__global__ void __launch_bounds__(256, 1) attn_kernel()
{
    extern __shared__ float smf[];
    const uint32_t sb = smem_u32(smf);
    uint32_t* W = (uint32_t*)smf;
    float*    Ss = smf + SS_OFF;
    uint32_t* Ssu = (uint32_t*)Ss;
    float*    corr_s = smf + CORR_OFF;
    float*    invl_s = smf + INVL_OFF;

    const int tid = threadIdx.x;
    const int wid = tid >> 5, lid = tid & 31;
    const int g = lid >> 2, tg = lid & 3;
    const int wm = (wid & 3) * 16;
    const int half = wid >> 2;
    const int tx = tid & 15, ty = tid >> 4;
    const int qx = 15 - (int)blockIdx.x;
    const int q0 = qx * 64;
    const int bh = blockIdx.y;
    const int b = bh >> 3, h = bh & 7;
    const int n_tiles = qx + 21;
    const int P0 = 15 - qx;

    const int ldr = tid >> 2;
    const int ldc0 = tid & 3;
    const float* peh = g_pe + (size_t)h * KV_ * 128;

    auto issueK = [&](int t) {
        const int m0 = (t < n_tiles) ? t * 64 : 0;
        const float* src = g_k + ((size_t)(b * KV_ + m0 + ldr)) * 1024 + h * 128;
        const uint32_t dst = sb + (KS_OFF + (t & 1) * 8448 + ldr * 132) * 4;
#pragma unroll
        for (int i = 0; i < 8; i++) { int c = ldc0 + 4 * i; cpa16(dst + c * 16, src + c * 4); }
    };
    auto issueV = [&](int t) {
        const int m0 = (t < n_tiles) ? t * 64 : 0;
        const float* src = g_v + ((size_t)(b * KV_ + m0 + ldr)) * 1024 + h * 128;
        const uint32_t dst = sb + (VS_OFF + ldr * 136) * 4;
#pragma unroll
        for (int i = 0; i < 8; i++) { int c = ldc0 + 4 * i; cpa16(dst + c * 16, src + c * 4); }
    };
    auto issuePE = [&](int page) {
        int r = page * 64 + ldr;
        if ((unsigned)r >= (unsigned)KV_) r = 0;
        const float* src = peh + (size_t)r * 128;
        const uint32_t dst = sb + (PE_OFF + (page & 1) * 8448 + ldr * 132) * 4;
#pragma unroll
        for (int i = 0; i < 8; i++) { int c = ldc0 + 4 * i; cpa16(dst + c * 16, src + c * 4); }
    };

    issueK(0); issuePE(P0); issuePE(P0 + 1);
    CP_COMMIT();
    issueV(0);
    CP_COMMIT();

    uint32_t qf[16][4];
    {
        const float* q0p = g_q + ((size_t)(b * T_ + q0 + wm + g)) * 1024 + h * 128;
        const float* q8p = q0p + 8 * 1024;
#pragma unroll
        for (int kb8 = 0; kb8 < 16; kb8++) {
            const int c = kb8 * 8 + tg;
            qf[kb8][0] = __float_as_uint(q0p[c]);
            qf[kb8][1] = __float_as_uint(q8p[c]);
            qf[kb8][2] = __float_as_uint(q0p[c + 4]);
            qf[kb8][3] = __float_as_uint(q8p[c + 4]);
        }
    }

    float o[8][4];
#pragma unroll
    for (int d = 0; d < 8; d++)
#pragma unroll
        for (int r = 0; r < 4; r++) o[d][r] = 0.f;
    float m_run[4], l_run[4];
#pragma unroll
    for (int i = 0; i < 4; i++) { m_run[i] = -INFINITY; l_run[i] = 0.f; }

    auto s2page = [&](int page) {
        const uint32_t* PEb = W + PE_OFF + (page & 1) * 8448;
        float* outp = smf + S2_OFF + (page & 1) * 4352;
        float c2[4][4];
#pragma unroll
        for (int vf = 0; vf < 4; vf++)
#pragma unroll
            for (int r = 0; r < 4; r++) c2[vf][r] = 0.f;
#pragma unroll
        for (int kb8 = 0; kb8 < 16; kb8++) {
            const int kb = kb8 * 8;
#pragma unroll
            for (int vf = 0; vf < 4; vf++) {
                const int n = half * 32 + vf * 8 + g;
                uint32_t b0 = PEb[n * 132 + kb + tg];
                uint32_t b1 = PEb[n * 132 + kb + tg + 4];
                MMA_TF32(c2[vf], qf[kb8][0], qf[kb8][1], qf[kb8][2], qf[kb8][3], b0, b1);
            }
        }
#pragma unroll
        for (int vf = 0; vf < 4; vf++) {
            const int col = half * 32 + vf * 8 + 2 * tg;
            *(float2*)(outp + (wm + g) * 68 + col) = make_float2(c2[vf][0], c2[vf][1]);
            *(float2*)(outp + (wm + g + 8) * 68 + col) = make_float2(c2[vf][2], c2[vf][3]);
        }
    };

    CP_WAIT(1);
    __syncthreads();
    s2page(P0);

    for (int t = 0; t < n_tiles; t++) {
        const int m0 = t * 64;
        const int Pb = t - qx + 15;

        CP_WAIT(1);
        __syncthreads();

        // ---- S1 = Q @ K^T ----
        {
            const uint32_t* Kw = W + KS_OFF + (t & 1) * 8448;
            float c1[4][4];
#pragma unroll
            for (int nf = 0; nf < 4; nf++)
#pragma unroll
                for (int r = 0; r < 4; r++) c1[nf][r] = 0.f;
#pragma unroll
            for (int kb8 = 0; kb8 < 16; kb8++) {
                const int kb = kb8 * 8;
#pragma unroll
                for (int nf = 0; nf < 4; nf++) {
                    const int n = half * 32 + nf * 8 + g;
                    uint32_t b0 = Kw[n * 132 + kb + tg];
                    uint32_t b1 = Kw[n * 132 + kb + tg + 4];
                    MMA_TF32(c1[nf], qf[kb8][0], qf[kb8][1], qf[kb8][2], qf[kb8][3], b0, b1);
                }
            }
#pragma unroll
            for (int nf = 0; nf < 4; nf++) {
                const int col = half * 32 + nf * 8 + 2 * tg;
                *(float2*)(Ss + (wm + g) * 68 + col) = make_float2(c1[nf][0], c1[nf][1]);
                *(float2*)(Ss + (wm + g + 8) * 68 + col) = make_float2(c1[nf][2], c1[nf][3]);
            }
        }

        s2page(Pb + 1);
        __syncthreads();

        issueK(t + 1); issuePE(Pb + 2);
        CP_COMMIT();

        // ---- softmax ----
        {
            const float* S2a = smf + S2_OFF + (Pb & 1) * 4352;
            const float* S2b = smf + S2_OFF + ((Pb + 1) & 1) * 4352;
#pragma unroll
            for (int ii = 0; ii < 4; ii++) {
                const int i = ty + 16 * ii;
                const int qg = q0 + i;
                float s[4];
#pragma unroll
                for (int jj = 0; jj < 4; jj++) {
                    const int j = tx + 16 * jj;
                    const int u = 63 + j - i;
                    float pv = (u < 64) ? S2a[i * 68 + u] : S2b[i * 68 + u - 64];
                    s[jj] = Ss[i * 68 + j] + pv;
                    if (m0 + j > qg + TOTMEM_) s[jj] = -INFINITY;
                }
                float mx = fmaxf(fmaxf(s[0], s[1]), fmaxf(s[2], s[3]));
                mx = fmaxf(mx, __shfl_xor_sync(0xffffffffu, mx, 1, 16));
                mx = fmaxf(mx, __shfl_xor_sync(0xffffffffu, mx, 2, 16));
                mx = fmaxf(mx, __shfl_xor_sync(0xffffffffu, mx, 4, 16));
                mx = fmaxf(mx, __shfl_xor_sync(0xffffffffu, mx, 8, 16));
                float m_new = fmaxf(m_run[ii], mx);
                float corrv = __expf(m_run[ii] - m_new);
                float p0 = __expf(s[0] - m_new);
                float p1 = __expf(s[1] - m_new);
                float p2 = __expf(s[2] - m_new);
                float p3 = __expf(s[3] - m_new);
                float sum = p0 + p1 + p2 + p3;
                sum += __shfl_xor_sync(0xffffffffu, sum, 1, 16);
                sum += __shfl_xor_sync(0xffffffffu, sum, 2, 16);
                sum += __shfl_xor_sync(0xffffffffu, sum, 4, 16);
                sum += __shfl_xor_sync(0xffffffffu, sum, 8, 16);
                l_run[ii] = l_run[ii] * corrv + sum;
                m_run[ii] = m_new;
                Ssu[i * 68 + tx]      = tf32r(p0);
                Ssu[i * 68 + tx + 16] = tf32r(p1);
                Ssu[i * 68 + tx + 32] = tf32r(p2);
                Ssu[i * 68 + tx + 48] = tf32r(p3);
                if (tx == 0) corr_s[i] = corrv;
            }
        }

        CP_WAIT(1);
        __syncthreads();

        // ---- PV ----
        {
            const uint32_t* Vw = W + VS_OFF;
            const float cr0 = corr_s[wm + g];
            const float cr8 = corr_s[wm + g + 8];
#pragma unroll
            for (int df = 0; df < 8; df++) {
                o[df][0] *= cr0; o[df][1] *= cr0;
                o[df][2] *= cr8; o[df][3] *= cr8;
            }
#pragma unroll
            for (int kb8 = 0; kb8 < 8; kb8++) {
                const int kb = kb8 * 8;
                uint32_t a0 = Ssu[(wm + g) * 68 + kb + tg];
                uint32_t a1 = Ssu[(wm + g + 8) * 68 + kb + tg];
                uint32_t a2 = Ssu[(wm + g) * 68 + kb + tg + 4];
                uint32_t a3 = Ssu[(wm + g + 8) * 68 + kb + tg + 4];
#pragma unroll
                for (int df = 0; df < 8; df++) {
                    uint32_t b0 = Vw[(kb + tg) * 136 + half * 64 + df * 8 + g];
                    uint32_t b1 = Vw[(kb + tg + 4) * 136 + half * 64 + df * 8 + g];
                    MMA_TF32(o[df], a0, a1, a2, a3, b0, b1);
                }
            }
        }
        __syncthreads();

        issueV(t + 1);
        CP_COMMIT();
    }

    CP_WAIT(0);
    if (tx == 0) {
#pragma unroll
        for (int ii = 0; ii < 4; ii++)
            invl_s[ty + 16 * ii] = 1.f / l_run[ii];
    }
    __syncthreads();
    const float il0 = invl_s[wm + g];
    const float il8 = invl_s[wm + g + 8];
    const int row0 = q0 + wm + g;
#pragma unroll
    for (int df = 0; df < 8; df++) {
        const int col = h * 128 + half * 64 + df * 8 + 2 * tg;
        *(float2*)(g_attn + ((size_t)(b * T_ + row0)) * 1024 + col) =
            make_float2(tf32f(o[df][0] * il0), tf32f(o[df][1] * il0));
        *(float2*)(g_attn + ((size_t)(b * T_ + row0 + 8)) * 1024 + col) =
            make_float2(tf32f(o[df][2] * il8), tf32f(o[df][3] * il8));
    }
}

// ---------------------------------------------------------------------------
extern "C" void kernel_launch(void* const* d_in, const int* in_sizes, int n_in,
                              void* d_out, int out_size)
{
    (void)in_sizes; (void)n_in; (void)out_size;
    const float* x      = (const float*)d_in[0];
    const float* mem    = (const float*)d_in[1];
    const float* cmem   = (const float*)d_in[2];
    const float* pe     = (const float*)d_in[3];
    const float* Wq     = (const float*)d_in[5];
    const float* Wkv    = (const float*)d_in[6];
    const float* Wout   = (const float*)d_in[7];
    const float* b_out  = (const float*)d_in[8];
    const float* conv_w = (const float*)d_in[9];
    const float* conv_b = (const float*)d_in[10];

    float* out = (float*)d_out;
    float* out_logits = out;
    float* out_cmem   = out + (size_t)2 * B_ * T_ * E_;

    cudaFuncSetAttribute(attn_kernel, cudaFuncAttributeMaxDynamicSharedMemorySize, ATT_SMEM);
    cudaFuncSetAttribute(qkv_cmem_kernel, cudaFuncAttributeMaxDynamicSharedMemorySize, PIPE_SMEM);
    cudaFuncSetAttribute(out_gemm, cudaFuncAttributeMaxDynamicSharedMemorySize, PIPE_SMEM);

    // 1) fused preprocessing (rounds, conv_w permute, new_mem copy, aux)
    pre_kernel<<<(SEG_TOTAL + 255) / 256, 256>>>(
        (const float4*)pe, (const float4*)x, (const float4*)mem, (const float4*)cmem,
        (const float4*)Wq, (const float4*)Wkv, (const float4*)Wout, (const float4*)conv_w,
        out);

    // 2) fused CMEM + KV + Q GEMMs
    qkv_cmem_kernel<<<1472, 256, PIPE_SMEM>>>(mem, conv_b, out_cmem);

    // 3) attention
    attn_kernel<<<dim3(16, 32), 256, ATT_SMEM>>>();

    // 4) logits = attn_out @ Wout + b_out
    out_gemm<<<dim3(8, 32), 256, PIPE_SMEM>>>(b_out, out_logits);
}

// round 15
// speedup vs baseline: 2.2679x; 1.0427x over previous
#include <cuda_runtime.h>
#include <cuda_bf16.h>
#include <math.h>
#include <stdint.h>

// Problem constants
#define B_ 4
#define T_ 1024
#define E_ 1024
#define H_ 8
#define DH_ 128
#define KV_ 2304
#define CML_ 256
#define MEML_ 1024
#define TOTMEM_ 1280
#define SCALE_ 0.08838834764831845f

// Scratch (device globals — allocation-free rule)
__device__ float g_q[B_ * T_ * E_];      // pre-scaled, tf32-rounded
__device__ float g_k[B_ * KV_ * E_];     // tf32-rounded
__device__ float g_v[B_ * KV_ * E_];     // tf32-rounded
__device__ float g_attn[B_ * T_ * E_];   // tf32-rounded (attn epilogue)
__device__ float g_pe[H_ * KV_ * DH_];   // tf32-rounded pos_emb
__device__ float g_cwt[1024 * 4096];     // conv_w permuted to (o, r*1024+d)
// pre-rounded GEMM inputs
__device__ float g_xr[B_ * T_ * E_];
__device__ float g_memr[B_ * MEML_ * E_];
__device__ float g_cmemr[B_ * CML_ * E_];
__device__ float g_wqr[1024 * 1024];
__device__ float g_wkvr[1024 * 2048];
__device__ float g_woutr[1024 * 1024];

__device__ __forceinline__ uint32_t tf32r(float f) {
    uint32_t r;
    asm("cvt.rna.tf32.f32 %0, %1;" : "=r"(r) : "f"(f));
    return r;
}
__device__ __forceinline__ float tf32f(float f) {
    return __uint_as_float(tf32r(f));
}

#define MMA_TF32(c, a0, a1, a2, a3, b0, b1) \
    asm volatile( \
        "mma.sync.aligned.m16n8k8.row.col.f32.tf32.tf32.f32 " \
        "{%0,%1,%2,%3}, {%4,%5,%6,%7}, {%8,%9}, {%0,%1,%2,%3};" \
        : "+f"((c)[0]), "+f"((c)[1]), "+f"((c)[2]), "+f"((c)[3]) \
        : "r"(a0), "r"(a1), "r"(a2), "r"(a3), "r"(b0), "r"(b1))

__device__ __forceinline__ uint32_t smem_u32(const void* p) {
    uint32_t a;
    asm("{ .reg .u64 t; cvta.to.shared.u64 t, %1; cvt.u32.u64 %0, t; }" : "=r"(a) : "l"(p));
    return a;
}
__device__ __forceinline__ void cpa16(uint32_t dst, const float* src) {
    asm volatile("cp.async.cg.shared.global [%0], [%1], 16;" :: "r"(dst), "l"(src));
}
#define CP_COMMIT() asm volatile("cp.async.commit_group;" ::: "memory")
#define CP_WAIT(n)  asm volatile("cp.async.wait_group %0;" :: "n"(n) : "memory")

// ---------------------------------------------------------------------------
// Shared pipelined-GEMM mainloop (inputs pre-rounded, K=1024, 3-stage)
// ---------------------------------------------------------------------------
#define AW 36
#define BW 136
#define ASTG (128 * AW)
#define BSTG (32 * BW)
#define STG  (ASTG + BSTG)
#define PIPE_SMEM (STG * 3 * 4)

__device__ __forceinline__ void pipe_loop(
    float* sm, uint32_t sb, const float* Abase, const float* Bbase, int ldbn,
    int tid, int wm, int wn, int g, int tg, float c[2][8][4])
{
    const int arow0 = tid >> 3;
    const int ac = (tid & 7) * 4;
    const int brow0 = tid >> 5;
    const int bc = (tid & 31) * 4;

    auto issue = [&](int t) {
        const uint32_t sa = sb + ((t % 3) * STG) * 4;
        const float* asrc = Abase + (size_t)arow0 * 1024 + t * 32 + ac;
#pragma unroll
        for (int ia = 0; ia < 4; ia++)
            cpa16(sa + ((arow0 + ia * 32) * AW + ac) * 4, asrc + (size_t)(ia * 32) * 1024);
        const uint32_t sB = sa + ASTG * 4;
        const float* bsrc = Bbase + (size_t)(t * 32 + brow0) * ldbn + bc;
#pragma unroll
        for (int ib = 0; ib < 4; ib++)
            cpa16(sB + ((brow0 + ib * 8) * BW + bc) * 4, bsrc + (size_t)(ib * 8) * ldbn);
    };

    issue(0); CP_COMMIT();
    issue(1); CP_COMMIT();

    for (int t = 0; t < 32; t++) {
        if (t < 31) { CP_WAIT(1); } else { CP_WAIT(0); }
        __syncthreads();
        if (t + 2 < 32) { issue(t + 2); CP_COMMIT(); }

        const uint32_t* Asu = (const uint32_t*)(sm + (t % 3) * STG);
        const uint32_t* Bsu = Asu + ASTG;
        const int r0a = (wm + g) * AW;
        const int r0b = (wm + 16 + g) * AW;
#pragma unroll
        for (int kk = 0; kk < 4; kk++) {
            const int kb = kk * 8;
            uint32_t a[2][4];
            a[0][0] = Asu[r0a + kb + tg];
            a[0][1] = Asu[r0a + 8 * AW + kb + tg];
            a[0][2] = Asu[r0a + kb + tg + 4];
            a[0][3] = Asu[r0a + 8 * AW + kb + tg + 4];
            a[1][0] = Asu[r0b + kb + tg];
            a[1][1] = Asu[r0b + 8 * AW + kb + tg];
            a[1][2] = Asu[r0b + kb + tg + 4];
            a[1][3] = Asu[r0b + 8 * AW + kb + tg + 4];
#pragma unroll
            for (int ni = 0; ni < 8; ni++) {
                uint32_t b0 = Bsu[(kb + tg) * BW + wn + 8 * ni + g];
                uint32_t b1 = Bsu[(kb + tg + 4) * BW + wn + 8 * ni + g];
#pragma unroll
                for (int mi = 0; mi < 2; mi++)
                    MMA_TF32(c[mi][ni], a[mi][0], a[mi][1], a[mi][2], a[mi][3], b0, b1);
            }
        }
    }
}

// ---------------------------------------------------------------------------
// Fused QKV + CMEM kernel (unchanged from round 13)
// ---------------------------------------------------------------------------
__global__ void __launch_bounds__(256, 2) qkv_cmem_kernel(
    const float* __restrict__ mem_raw, const float* __restrict__ conv_b,
    float* __restrict__ out_cmem)
{
    extern __shared__ float sm[];
    const uint32_t sb = smem_u32(sm);
    const int tid = threadIdx.x;
    const int wid = tid >> 5, lid = tid & 31;
    const int g = lid >> 2, tg = lid & 3;
    const int wm = (wid & 3) * 32;
    const int wn = (wid >> 2) * 64;
    const int idx = blockIdx.x;

    if (idx < 64) {
        const int n0 = (idx & 7) * 128;
        const int m0 = (idx >> 3) * 128;
        uint32_t* As = (uint32_t*)sm;
        uint32_t* Bs = As + 32 * 132;

        const float* Abase = mem_raw + (size_t)m0 * 4096;
        const float* Bbase = g_cwt + (size_t)n0 * 4096;

        const int arow = tid >> 1;
        const int akh  = (tid & 1) * 16;
        const float* aPtr = Abase + (size_t)arow * 4096 + akh;
        const float* bPtr = Bbase + (size_t)arow * 4096 + akh;

        float4 av[4], bv[4];
        auto loadT = [&](int t) {
#pragma unroll
            for (int j = 0; j < 4; j++) av[j] = *(const float4*)(aPtr + t * 32 + 4 * j);
#pragma unroll
            for (int j = 0; j < 4; j++) bv[j] = *(const float4*)(bPtr + t * 32 + 4 * j);
        };
        auto stsT = [&]() {
#pragma unroll
            for (int j = 0; j < 4; j++) {
                As[(akh + 4 * j + 0) * 132 + arow] = tf32r(av[j].x);
                As[(akh + 4 * j + 1) * 132 + arow] = tf32r(av[j].y);
                As[(akh + 4 * j + 2) * 132 + arow] = tf32r(av[j].z);
                As[(akh + 4 * j + 3) * 132 + arow] = tf32r(av[j].w);
                Bs[(akh + 4 * j + 0) * 132 + arow] = tf32r(bv[j].x);
                Bs[(akh + 4 * j + 1) * 132 + arow] = tf32r(bv[j].y);
                Bs[(akh + 4 * j + 2) * 132 + arow] = tf32r(bv[j].z);
                Bs[(akh + 4 * j + 3) * 132 + arow] = tf32r(bv[j].w);
            }
        };

        float c[2][8][4];
#pragma unroll
        for (int mi = 0; mi < 2; mi++)
#pragma unroll
            for (int ni = 0; ni < 8; ni++)
#pragma unroll
                for (int r = 0; r < 4; r++) c[mi][ni][r] = 0.f;

        loadT(0);
        for (int t = 0; t < 128; t++) {
            stsT();
            __syncthreads();
            if (t + 1 < 128) loadT(t + 1);
#pragma unroll
            for (int kk = 0; kk < 4; kk++) {
                const int kb = kk * 8;
                uint32_t a[2][4];
#pragma unroll
                for (int mi = 0; mi < 2; mi++) {
                    a[mi][0] = As[(kb + tg) * 132 + wm + 16 * mi + g];
                    a[mi][1] = As[(kb + tg) * 132 + wm + 16 * mi + g + 8];
                    a[mi][2] = As[(kb + tg + 4) * 132 + wm + 16 * mi + g];
                    a[mi][3] = As[(kb + tg + 4) * 132 + wm + 16 * mi + g + 8];
                }
#pragma unroll
                for (int ni = 0; ni < 8; ni++) {
                    uint32_t b0 = Bs[(kb + tg) * 132 + wn + 8 * ni + g];
                    uint32_t b1 = Bs[(kb + tg + 4) * 132 + wn + 8 * ni + g];
#pragma unroll
                    for (int mi = 0; mi < 2; mi++)
                        MMA_TF32(c[mi][ni], a[mi][0], a[mi][1], a[mi][2], a[mi][3], b0, b1);
                }
            }
            __syncthreads();
        }

#pragma unroll
        for (int mi = 0; mi < 2; mi++) {
            const int row = m0 + wm + 16 * mi + g;
#pragma unroll
            for (int ni = 0; ni < 8; ni++) {
                const int col = n0 + wn + 8 * ni + 2 * tg;
                float2 bb = *(const float2*)(conv_b + col);
                *(float2*)(out_cmem + (size_t)row * 1024 + col) =
                    make_float2(c[mi][ni][0] + bb.x, c[mi][ni][1] + bb.y);
                *(float2*)(out_cmem + (size_t)(row + 8) * 1024 + col) =
                    make_float2(c[mi][ni][2] + bb.x, c[mi][ni][3] + bb.y);
            }
        }
        return;
    }

    int mode, m0, n0, ldbn;
    const float *Abase, *Bbase;
    if (idx < 1216) {
        const int i2 = idx - 64;
        n0 = (i2 & 15) * 128;
        m0 = (i2 >> 4) * 128;
        mode = 1;
        ldbn = 2048;
        int b = m0 / KV_;
        int j = m0 - b * KV_;
        if (j < CML_)              Abase = g_cmemr + (size_t)(b * CML_ + j) * 1024;
        else if (j < CML_ + MEML_) Abase = g_memr + (size_t)(b * MEML_ + (j - CML_)) * 1024;
        else                       Abase = g_xr + (size_t)(b * T_ + (j - CML_ - MEML_)) * 1024;
        Bbase = g_wkvr + n0;
    } else {
        const int i3 = idx - 1216;
        n0 = (i3 & 7) * 128;
        m0 = (i3 >> 3) * 128;
        mode = 0;
        ldbn = 1024;
        Abase = g_xr + (size_t)m0 * 1024;
        Bbase = g_wqr + n0;
    }

    float c[2][8][4];
#pragma unroll
    for (int mi = 0; mi < 2; mi++)
#pragma unroll
        for (int ni = 0; ni < 8; ni++)
#pragma unroll
            for (int r = 0; r < 4; r++) c[mi][ni][r] = 0.f;

    pipe_loop(sm, sb, Abase, Bbase, ldbn, tid, wm, wn, g, tg, c);

#pragma unroll
    for (int mi = 0; mi < 2; mi++) {
        const int row = m0 + wm + 16 * mi + g;
#pragma unroll
        for (int ni = 0; ni < 8; ni++) {
            const int col = n0 + wn + 8 * ni + 2 * tg;
            float2 lo = make_float2(c[mi][ni][0], c[mi][ni][1]);
            float2 hi = make_float2(c[mi][ni][2], c[mi][ni][3]);
            if (mode == 0) {
                *(float2*)(g_q + (size_t)row * 1024 + col) =
                    make_float2(tf32f(lo.x * SCALE_), tf32f(lo.y * SCALE_));
                *(float2*)(g_q + (size_t)(row + 8) * 1024 + col) =
                    make_float2(tf32f(hi.x * SCALE_), tf32f(hi.y * SCALE_));
            } else {
                float* base = (n0 < 1024) ? g_k : g_v;
                int cc = (n0 < 1024) ? col : col - 1024;
                *(float2*)(base + (size_t)row * 1024 + cc) =
                    make_float2(tf32f(lo.x), tf32f(lo.y));
                *(float2*)(base + (size_t)(row + 8) * 1024 + cc) =
                    make_float2(tf32f(hi.x), tf32f(hi.y));
            }
        }
    }
}

// ---------------------------------------------------------------------------
// OUT GEMM (unchanged)
// ---------------------------------------------------------------------------
__global__ void __launch_bounds__(256, 2) out_gemm(
    const float* __restrict__ bias, float* __restrict__ Cout)
{
    extern __shared__ float sm[];
    const uint32_t sb = smem_u32(sm);
    const int tid = threadIdx.x;
    const int wid = tid >> 5, lid = tid & 31;
    const int g = lid >> 2, tg = lid & 3;
    const int wm = (wid & 3) * 32;
    const int wn = (wid >> 2) * 64;
    const int m0 = blockIdx.y * 128;
    const int n0 = blockIdx.x * 128;

    const float* Abase = g_attn + (size_t)m0 * 1024;
    const float* Bbase = g_woutr + n0;

    float c[2][8][4];
#pragma unroll
    for (int mi = 0; mi < 2; mi++)
#pragma unroll
        for (int ni = 0; ni < 8; ni++)
#pragma unroll
            for (int r = 0; r < 4; r++) c[mi][ni][r] = 0.f;

    pipe_loop(sm, sb, Abase, Bbase, 1024, tid, wm, wn, g, tg, c);

#pragma unroll
    for (int mi = 0; mi < 2; mi++) {
        const int row = m0 + wm + 16 * mi + g;
#pragma unroll
        for (int ni = 0; ni < 8; ni++) {
            const int col = n0 + wn + 8 * ni + 2 * tg;
            float2 bb = *(const float2*)(bias + col);
            *(float2*)(Cout + (size_t)row * 1024 + col) =
                make_float2(c[mi][ni][0] + bb.x, c[mi][ni][1] + bb.y);
            *(float2*)(Cout + (size_t)(row + 8) * 1024 + col) =
                make_float2(c[mi][ni][2] + bb.x, c[mi][ni][3] + bb.y);
        }
    }
}

// ---------------------------------------------------------------------------
// Fused preprocessing (unchanged)
// ---------------------------------------------------------------------------
#define SEG_PE    589824u
#define SEG_X     1638400u
#define SEG_MEM   2686976u
#define SEG_CMEM  2949120u
#define SEG_WQ    3211264u
#define SEG_WKV   3735552u
#define SEG_WOUT  3997696u
#define SEG_XCOPY 5046272u
#define SEG_TOTAL 6094848u

__global__ void pre_kernel(
    const float4* __restrict__ pe, const float4* __restrict__ x,
    const float4* __restrict__ mem, const float4* __restrict__ cmem,
    const float4* __restrict__ Wq, const float4* __restrict__ Wkv,
    const float4* __restrict__ Wout, const float4* __restrict__ conv_w,
    float* __restrict__ out)
{
    const uint32_t i = blockIdx.x * 256 + threadIdx.x;
    if (i >= SEG_TOTAL) return;

    auto r4 = [](float4 v) {
        return make_float4(tf32f(v.x), tf32f(v.y), tf32f(v.z), tf32f(v.w));
    };

    if (i < SEG_PE) {
        ((float4*)g_pe)[i] = r4(pe[i]);
    } else if (i < SEG_X) {
        uint32_t j = i - SEG_PE;
        ((float4*)g_xr)[j] = r4(x[j]);
    } else if (i < SEG_MEM) {
        uint32_t j = i - SEG_X;
        ((float4*)g_memr)[j] = r4(mem[j]);
    } else if (i < SEG_CMEM) {
        uint32_t j = i - SEG_MEM;
        ((float4*)g_cmemr)[j] = r4(cmem[j]);
    } else if (i < SEG_WQ) {
        uint32_t j = i - SEG_CMEM;
        ((float4*)g_wqr)[j] = r4(Wq[j]);
    } else if (i < SEG_WKV) {
        uint32_t j = i - SEG_WQ;
        ((float4*)g_wkvr)[j] = r4(Wkv[j]);
    } else if (i < SEG_WOUT) {
        uint32_t j = i - SEG_WKV;
        ((float4*)g_woutr)[j] = r4(Wout[j]);
    } else if (i < SEG_XCOPY) {
        uint32_t j = i - SEG_WOUT;
        ((float4*)(out + (size_t)B_ * T_ * E_))[j] = x[j];
        if (j == 0)
            out[(size_t)B_ * T_ * E_ * 2 + (size_t)B_ * CML_ * E_] = 0.f;
    } else {
        uint32_t j = i - SEG_XCOPY;
        uint32_t o = j >> 10, d = j & 1023;
        float4 v = conv_w[j];
        float* dst = g_cwt + (size_t)o * 4096 + d;
        dst[0]    = v.x;
        dst[1024] = v.y;
        dst[2048] = v.z;
        dst[3072] = v.w;
    }
}

// ---------------------------------------------------------------------------
// Tensor-core flash attention v4 (fixed): 512 threads / 16 warps.
// S1/S2: warps tile (4 m-bands x 4 col-quarters of 16).
// PV/out: warps tile (4 m-bands x 4 d-quarters of 32) -> full 128 head dims.
// ---------------------------------------------------------------------------
#define KS_OFF   0
#define PE_OFF   16896
#define VS_OFF   33792
#define SS_OFF   42496
#define S2_OFF   46848
#define CORR_OFF 55552
#define INVL_OFF 55616
#define ATT_SMEM (55680 * 4)

__global__ void __launch_bounds__(512, 1) attn_kernel()
{
    extern __shared__ float smf[];
    const uint32_t sb = smem_u32(smf);
    uint32_t* W = (uint32_t*)smf;
    float*    Ss = smf + SS_OFF;
    uint32_t* Ssu = (uint32_t*)Ss;
    float*    corr_s = smf + CORR_OFF;
    float*    invl_s = smf + INVL_OFF;

    const int tid = threadIdx.x;
    const int wid = tid >> 5, lid = tid & 31;
    const int g = lid >> 2, tg = lid & 3;
    const int wm = (wid & 3) * 16;       // m-band (16 rows)
    const int qr = wid >> 2;             // quarter 0..3
    const int tx = tid & 15;
    const int ty2 = tid >> 4;            // 0..31 (each thread: rows ty2, ty2+32)
    const int qx = 15 - (int)blockIdx.x;
    const int q0 = qx * 64;
    const int bh = blockIdx.y;
    const int b = bh >> 3, h = bh & 7;
    const int n_tiles = qx + 21;
    const int P0 = 15 - qx;

    const int ldr = tid >> 3;            // 0..63 (row), 8 threads/row
    const int ldc0 = tid & 7;
    const float* peh = g_pe + (size_t)h * KV_ * 128;

    auto issueK = [&](int t) {
        const int m0 = (t < n_tiles) ? t * 64 : 0;
        const float* src = g_k + ((size_t)(b * KV_ + m0 + ldr)) * 1024 + h * 128;
        const uint32_t dst = sb + (KS_OFF + (t & 1) * 8448 + ldr * 132) * 4;
#pragma unroll
        for (int i = 0; i < 4; i++) { int c = ldc0 + 8 * i; cpa16(dst + c * 16, src + c * 4); }
    };
    auto issueV = [&](int t) {
        const int m0 = (t < n_tiles) ? t * 64 : 0;
        const float* src = g_v + ((size_t)(b * KV_ + m0 + ldr)) * 1024 + h * 128;
        const uint32_t dst = sb + (VS_OFF + ldr * 136) * 4;
#pragma unroll
        for (int i = 0; i < 4; i++) { int c = ldc0 + 8 * i; cpa16(dst + c * 16, src + c * 4); }
    };
    auto issuePE = [&](int page) {
        int r = page * 64 + ldr;
        if ((unsigned)r >= (unsigned)KV_) r = 0;
        const float* src = peh + (size_t)r * 128;
        const uint32_t dst = sb + (PE_OFF + (page & 1) * 8448 + ldr * 132) * 4;
#pragma unroll
        for (int i = 0; i < 4; i++) { int c = ldc0 + 8 * i; cpa16(dst + c * 16, src + c * 4); }
    };

    issueK(0); issuePE(P0); issuePE(P0 + 1);
    CP_COMMIT();
    issueV(0);
    CP_COMMIT();

    // Q fragments -> registers (rows wm..wm+15, full K)
    uint32_t qf[16][4];
    {
        const float* q0p = g_q + ((size_t)(b * T_ + q0 + wm + g)) * 1024 + h * 128;
        const float* q8p = q0p + 8 * 1024;
#pragma unroll
        for (int kb8 = 0; kb8 < 16; kb8++) {
            const int c = kb8 * 8 + tg;
            qf[kb8][0] = __float_as_uint(q0p[c]);
            qf[kb8][1] = __float_as_uint(q8p[c]);
            qf[kb8][2] = __float_as_uint(q0p[c + 4]);
            qf[kb8][3] = __float_as_uint(q8p[c + 4]);
        }
    }

    float o[4][4];
#pragma unroll
    for (int d = 0; d < 4; d++)
#pragma unroll
        for (int r = 0; r < 4; r++) o[d][r] = 0.f;
    float m_run[2], l_run[2];
#pragma unroll
    for (int i = 0; i < 2; i++) { m_run[i] = -INFINITY; l_run[i] = 0.f; }

    // S2 page GEMM: warp computes rows wm..wm+15 x u-cols qr*16..+16
    auto s2page = [&](int page) {
        const uint32_t* PEb = W + PE_OFF + (page & 1) * 8448;
        float* outp = smf + S2_OFF + (page & 1) * 4352;
        float c2[2][4];
#pragma unroll
        for (int vf = 0; vf < 2; vf++)
#pragma unroll
            for (int r = 0; r < 4; r++) c2[vf][r] = 0.f;
#pragma unroll
        for (int kb8 = 0; kb8 < 16; kb8++) {
            const int kb = kb8 * 8;
#pragma unroll
            for (int vf = 0; vf < 2; vf++) {
                const int n = qr * 16 + vf * 8 + g;
                uint32_t b0 = PEb[n * 132 + kb + tg];
                uint32_t b1 = PEb[n * 132 + kb + tg + 4];
                MMA_TF32(c2[vf], qf[kb8][0], qf[kb8][1], qf[kb8][2], qf[kb8][3], b0, b1);
            }
        }
#pragma unroll
        for (int vf = 0; vf < 2; vf++) {
            const int col = qr * 16 + vf * 8 + 2 * tg;
            *(float2*)(outp + (wm + g) * 68 + col) = make_float2(c2[vf][0], c2[vf][1]);
            *(float2*)(outp + (wm + g + 8) * 68 + col) = make_float2(c2[vf][2], c2[vf][3]);
        }
    };

    CP_WAIT(1);
    __syncthreads();
    s2page(P0);

    for (int t = 0; t < n_tiles; t++) {
        const int m0 = t * 64;
        const int Pb = t - qx + 15;

        CP_WAIT(1);
        __syncthreads();

        // ---- S1 = Q @ K^T (warp: 16 rows x 16 cols) ----
        {
            const uint32_t* Kw = W + KS_OFF + (t & 1) * 8448;
            float c1[2][4];
#pragma unroll
            for (int nf = 0; nf < 2; nf++)
#pragma unroll
                for (int r = 0; r < 4; r++) c1[nf][r] = 0.f;
#pragma unroll
            for (int kb8 = 0; kb8 < 16; kb8++) {
                const int kb = kb8 * 8;
#pragma unroll
                for (int nf = 0; nf < 2; nf++) {
                    const int n = qr * 16 + nf * 8 + g;
                    uint32_t b0 = Kw[n * 132 + kb + tg];
                    uint32_t b1 = Kw[n * 132 + kb + tg + 4];
                    MMA_TF32(c1[nf], qf[kb8][0], qf[kb8][1], qf[kb8][2], qf[kb8][3], b0, b1);
                }
            }
#pragma unroll
            for (int nf = 0; nf < 2; nf++) {
                const int col = qr * 16 + nf * 8 + 2 * tg;
                *(float2*)(Ss + (wm + g) * 68 + col) = make_float2(c1[nf][0], c1[nf][1]);
                *(float2*)(Ss + (wm + g + 8) * 68 + col) = make_float2(c1[nf][2], c1[nf][3]);
            }
        }

        s2page(Pb + 1);
        __syncthreads();

        issueK(t + 1); issuePE(Pb + 2);
        CP_COMMIT();

        // ---- softmax: each thread rows {ty2, ty2+32}, cols tx+16jj ----
        {
            const float* S2a = smf + S2_OFF + (Pb & 1) * 4352;
            const float* S2b = smf + S2_OFF + ((Pb + 1) & 1) * 4352;
#pragma unroll
            for (int ii = 0; ii < 2; ii++) {
                const int i = ty2 + 32 * ii;
                const int qg = q0 + i;
                float s[4];
#pragma unroll
                for (int jj = 0; jj < 4; jj++) {
                    const int j = tx + 16 * jj;
                    const int u = 63 + j - i;
                    float pv = (u < 64) ? S2a[i * 68 + u] : S2b[i * 68 + u - 64];
                    s[jj] = Ss[i * 68 + j] + pv;
                    if (m0 + j > qg + TOTMEM_) s[jj] = -INFINITY;
                }
                float mx = fmaxf(fmaxf(s[0], s[1]), fmaxf(s[2], s[3]));
                mx = fmaxf(mx, __shfl_xor_sync(0xffffffffu, mx, 1, 16));
                mx = fmaxf(mx, __shfl_xor_sync(0xffffffffu, mx, 2, 16));
                mx = fmaxf(mx, __shfl_xor_sync(0xffffffffu, mx, 4, 16));
                mx = fmaxf(mx, __shfl_xor_sync(0xffffffffu, mx, 8, 16));
                float m_new = fmaxf(m_run[ii], mx);
                float corrv = __expf(m_run[ii] - m_new);
                float p0 = __expf(s[0] - m_new);
                float p1 = __expf(s[1] - m_new);
                float p2 = __expf(s[2] - m_new);
                float p3 = __expf(s[3] - m_new);
                float sum = p0 + p1 + p2 + p3;
                sum += __shfl_xor_sync(0xffffffffu, sum, 1, 16);
                sum += __shfl_xor_sync(0xffffffffu, sum, 2, 16);
                sum += __shfl_xor_sync(0xffffffffu, sum, 4, 16);
                sum += __shfl_xor_sync(0xffffffffu, sum, 8, 16);
                l_run[ii] = l_run[ii] * corrv + sum;
                m_run[ii] = m_new;
                Ssu[i * 68 + tx]      = tf32r(p0);
                Ssu[i * 68 + tx + 16] = tf32r(p1);
                Ssu[i * 68 + tx + 32] = tf32r(p2);
                Ssu[i * 68 + tx + 48] = tf32r(p3);
                if (tx == 0) corr_s[i] = corrv;
            }
        }

        CP_WAIT(1);
        __syncthreads();

        // ---- PV: warp computes rows wm..wm+15 x d-cols qr*32..+32 ----
        {
            const uint32_t* Vw = W + VS_OFF;
            const float cr0 = corr_s[wm + g];
            const float cr8 = corr_s[wm + g + 8];
#pragma unroll
            for (int df = 0; df < 4; df++) {
                o[df][0] *= cr0; o[df][1] *= cr0;
                o[df][2] *= cr8; o[df][3] *= cr8;
            }
#pragma unroll
            for (int kb8 = 0; kb8 < 8; kb8++) {
                const int kb = kb8 * 8;
                uint32_t a0 = Ssu[(wm + g) * 68 + kb + tg];
                uint32_t a1 = Ssu[(wm + g + 8) * 68 + kb + tg];
                uint32_t a2 = Ssu[(wm + g) * 68 + kb + tg + 4];
                uint32_t a3 = Ssu[(wm + g + 8) * 68 + kb + tg + 4];
#pragma unroll
                for (int df = 0; df < 4; df++) {
                    uint32_t b0 = Vw[(kb + tg) * 136 + qr * 32 + df * 8 + g];
                    uint32_t b1 = Vw[(kb + tg + 4) * 136 + qr * 32 + df * 8 + g];
                    MMA_TF32(o[df], a0, a1, a2, a3, b0, b1);
                }
            }
        }
        __syncthreads();

        issueV(t + 1);
        CP_COMMIT();
    }

    CP_WAIT(0);
    if (tx == 0) {
#pragma unroll
        for (int ii = 0; ii < 2; ii++)
            invl_s[ty2 + 32 * ii] = 1.f / l_run[ii];
    }
    __syncthreads();
    const float il0 = invl_s[wm + g];
    const float il8 = invl_s[wm + g + 8];
    const int row0 = q0 + wm + g;
#pragma unroll
    for (int df = 0; df < 4; df++) {
        const int col = h * 128 + qr * 32 + df * 8 + 2 * tg;
        *(float2*)(g_attn + ((size_t)(b * T_ + row0)) * 1024 + col) =
            make_float2(tf32f(o[df][0] * il0), tf32f(o[df][1] * il0));
        *(float2*)(g_attn + ((size_t)(b * T_ + row0 + 8)) * 1024 + col) =
            make_float2(tf32f(o[df][2] * il8), tf32f(o[df][3] * il8));
    }
}

// ---------------------------------------------------------------------------
extern "C" void kernel_launch(void* const* d_in, const int* in_sizes, int n_in,
                              void* d_out, int out_size)
{
    (void)in_sizes; (void)n_in; (void)out_size;
    const float* x      = (const float*)d_in[0];
    const float* mem    = (const float*)d_in[1];
    const float* cmem   = (const float*)d_in[2];
    const float* pe     = (const float*)d_in[3];
    const float* Wq     = (const float*)d_in[5];
    const float* Wkv    = (const float*)d_in[6];
    const float* Wout   = (const float*)d_in[7];
    const float* b_out  = (const float*)d_in[8];
    const float* conv_w = (const float*)d_in[9];
    const float* conv_b = (const float*)d_in[10];

    float* out = (float*)d_out;
    float* out_logits = out;
    float* out_cmem   = out + (size_t)2 * B_ * T_ * E_;

    cudaFuncSetAttribute(attn_kernel, cudaFuncAttributeMaxDynamicSharedMemorySize, ATT_SMEM);
    cudaFuncSetAttribute(qkv_cmem_kernel, cudaFuncAttributeMaxDynamicSharedMemorySize, PIPE_SMEM);
    cudaFuncSetAttribute(out_gemm, cudaFuncAttributeMaxDynamicSharedMemorySize, PIPE_SMEM);

    pre_kernel<<<(SEG_TOTAL + 255) / 256, 256>>>(
        (const float4*)pe, (const float4*)x, (const float4*)mem, (const float4*)cmem,
        (const float4*)Wq, (const float4*)Wkv, (const float4*)Wout, (const float4*)conv_w,
        out);

    qkv_cmem_kernel<<<1472, 256, PIPE_SMEM>>>(mem, conv_b, out_cmem);

    attn_kernel<<<dim3(16, 32), 512, ATT_SMEM>>>();

    out_gemm<<<dim3(8, 32), 256, PIPE_SMEM>>>(b_out, out_logits);
}